// round 1
// baseline (speedup 1.0000x reference)
#include <cuda_runtime.h>

#define BDIM 2
#define NDIM 1000
#define EDIM 2000
#define HDIM 128

// Scratch (device globals — no allocation allowed in kernel_launch)
__device__ float g_emb[BDIM * EDIM * HDIM];   // n2e_emb, flat rows r = b*E + e
__device__ float g_new[BDIM * EDIM * HDIM];   // new_n2e, same layout
__device__ float g_inv[BDIM * NDIM];          // 1 / (rowsum(edge2node) + 1)

// ---------------------------------------------------------------------------
// Kernel A: g_emb[b*E+e][h] = sum_n node2edge[b,e,n] * node_state[b,n,h]
// GEMM per batch: M=2000, K=1000, N=128. BM=32, BK=40 (25 exact K-iters).
// grid = (ceil(E/32)=63, B)
// ---------------------------------------------------------------------------
__global__ void __launch_bounds__(256) k_n2e(const float* __restrict__ n2e,
                                             const float* __restrict__ ns) {
    const int BK = 40;
    __shared__ float As[32][BK + 1];        // [m][k]
    __shared__ float Bs[BK][HDIM + 1];      // [k][h], pad 129 -> conflict-free

    int b  = blockIdx.y;
    int e0 = blockIdx.x * 32;
    int t  = threadIdx.x;
    int ng = t & 31;        // col group (strided cols ng + 32*n)
    int mg = t >> 5;        // row group (rows mg*4 .. mg*4+3)

    const float* Arow = n2e + (long)b * EDIM * NDIM;
    const float* Bmat = ns  + (long)b * NDIM * HDIM;

    float acc[4][4];
#pragma unroll
    for (int m = 0; m < 4; m++)
#pragma unroll
        for (int n = 0; n < 4; n++) acc[m][n] = 0.f;

    for (int k0 = 0; k0 < NDIM; k0 += BK) {
        for (int i = t; i < 32 * BK; i += 256) {
            int m = i / BK, k = i - m * BK;
            int e = e0 + m;
            As[m][k] = (e < EDIM) ? Arow[(long)e * NDIM + k0 + k] : 0.f;
        }
        for (int i = t; i < BK * HDIM; i += 256) {
            int k = i >> 7, h = i & 127;
            Bs[k][h] = Bmat[(long)(k0 + k) * HDIM + h];
        }
        __syncthreads();
#pragma unroll 8
        for (int k = 0; k < BK; k++) {
            float bv[4];
#pragma unroll
            for (int n = 0; n < 4; n++) bv[n] = Bs[k][ng + 32 * n];
#pragma unroll
            for (int m = 0; m < 4; m++) {
                float a = As[mg * 4 + m][k];
#pragma unroll
                for (int n = 0; n < 4; n++) acc[m][n] += a * bv[n];
            }
        }
        __syncthreads();
    }

#pragma unroll
    for (int m = 0; m < 4; m++) {
        int e = e0 + mg * 4 + m;
        if (e < EDIM) {
            float* o = g_emb + ((long)b * EDIM + e) * HDIM;
#pragma unroll
            for (int n = 0; n < 4; n++) o[ng + 32 * n] = acc[m][n];
        }
    }
}

// ---------------------------------------------------------------------------
// Kernel B (dominant, 8.4 GMAC):
//   g_new[r][i] = sum_h ev[r][h] * ( sum_j EN[h,i,j] * g_emb[r][j] )
// r = b*E+e in [0,4000). BM=32 rows/block -> 125 blocks exactly.
// Per h: inner GEMM emb(32x128) x EN[h]^T -> tt, then acc += ev[r][h]*tt.
// EN tile kept [i][j] with row pad 33; cols mapped strided (ng+32n) so the
// en_s column reads are bank-conflict-free. ev read via broadcast LDG (L1 hit).
// ---------------------------------------------------------------------------
__global__ void __launch_bounds__(256) k_econv(const float* __restrict__ ev,
                                               const float* __restrict__ EN) {
    __shared__ float emb_s[32][HDIM];        // 16 KB, broadcast reads
    __shared__ float en_s[HDIM][33];         // 16.9 KB, [i][j-chunk of 32]

    int r0 = blockIdx.x * 32;
    int t  = threadIdx.x;
    int ng = t & 31;
    int mg = t >> 5;

    for (int i = t; i < 32 * HDIM; i += 256) {
        int m = i >> 7, h = i & 127;
        emb_s[m][h] = g_emb[(long)(r0 + m) * HDIM + h];
    }
    __syncthreads();

    float acc[4][4];
#pragma unroll
    for (int m = 0; m < 4; m++)
#pragma unroll
        for (int n = 0; n < 4; n++) acc[m][n] = 0.f;

    for (int h = 0; h < HDIM; h++) {
        const float* ENh = EN + (long)h * HDIM * HDIM;
        float tt[4][4];
#pragma unroll
        for (int m = 0; m < 4; m++)
#pragma unroll
            for (int n = 0; n < 4; n++) tt[m][n] = 0.f;

        for (int jc = 0; jc < HDIM; jc += 32) {
            __syncthreads();
            for (int i = t; i < HDIM * 32; i += 256) {
                int ii = i >> 5, j = i & 31;
                en_s[ii][j] = ENh[ii * HDIM + jc + j];   // coalesced, CF store
            }
            __syncthreads();
#pragma unroll 8
            for (int j = 0; j < 32; j++) {
                float bv[4], e[4];
#pragma unroll
                for (int n = 0; n < 4; n++) bv[n] = en_s[ng + 32 * n][j];
#pragma unroll
                for (int m = 0; m < 4; m++) e[m] = emb_s[mg * 4 + m][jc + j];
#pragma unroll
                for (int m = 0; m < 4; m++)
#pragma unroll
                    for (int n = 0; n < 4; n++) tt[m][n] += e[m] * bv[n];
            }
        }
#pragma unroll
        for (int m = 0; m < 4; m++) {
            float w = __ldg(&ev[(long)(r0 + mg * 4 + m) * HDIM + h]); // warp bcast
#pragma unroll
            for (int n = 0; n < 4; n++) acc[m][n] += w * tt[m][n];
        }
    }

#pragma unroll
    for (int m = 0; m < 4; m++) {
        float* o = g_new + (long)(r0 + mg * 4 + m) * HDIM;
#pragma unroll
        for (int n = 0; n < 4; n++) o[ng + 32 * n] = acc[m][n];
    }
}

// ---------------------------------------------------------------------------
// Norm kernel: g_inv[b*N+n] = 1 / (1 + sum_e edge2node[b,n,e])
// ---------------------------------------------------------------------------
__global__ void __launch_bounds__(256) k_norm(const float* __restrict__ e2n) {
    __shared__ float red[256];
    int row = blockIdx.x;                 // 0..B*N-1 (flat, contiguous)
    const float* p = e2n + (long)row * EDIM;
    float s = 0.f;
    for (int e = threadIdx.x; e < EDIM; e += 256) s += p[e];
    red[threadIdx.x] = s;
    __syncthreads();
    for (int o = 128; o > 0; o >>= 1) {
        if (threadIdx.x < o) red[threadIdx.x] += red[threadIdx.x + o];
        __syncthreads();
    }
    if (threadIdx.x == 0) g_inv[row] = 1.f / (1.f + red[0]);
}

// ---------------------------------------------------------------------------
// Kernel C: out[b,n,i] = (sum_e edge2node[b,n,e]*g_new[b*E+e][i]
//                         + node_state[b,n,i]) * g_inv[b*N+n]
// GEMM per batch: M=1000, K=2000, N=128. BM=16 -> grid (63, B) = 126 blocks.
// ---------------------------------------------------------------------------
__global__ void __launch_bounds__(256) k_agg(const float* __restrict__ e2n,
                                             const float* __restrict__ ns,
                                             float* __restrict__ out) {
    const int BK = 32;
    __shared__ float As[16][BK + 1];
    __shared__ float Bs[BK][HDIM + 1];

    int b  = blockIdx.y;
    int n0 = blockIdx.x * 16;
    int t  = threadIdx.x;
    int ng = t & 31;
    int mg = t >> 5;                  // rows mg*2, mg*2+1

    const float* Arow = e2n  + (long)b * NDIM * EDIM;
    const float* Bmat = g_new + (long)b * EDIM * HDIM;

    float acc[2][4];
#pragma unroll
    for (int m = 0; m < 2; m++)
#pragma unroll
        for (int n = 0; n < 4; n++) acc[m][n] = 0.f;

    for (int k0 = 0; k0 < EDIM; k0 += BK) {
        for (int i = t; i < 16 * BK; i += 256) {
            int m = i >> 5, k = i & 31;
            int nn = n0 + m;
            As[m][k] = (nn < NDIM && k0 + k < EDIM)
                         ? Arow[(long)nn * EDIM + k0 + k] : 0.f;
        }
        for (int i = t; i < BK * HDIM; i += 256) {
            int k = i >> 7, h = i & 127;
            Bs[k][h] = (k0 + k < EDIM) ? Bmat[(long)(k0 + k) * HDIM + h] : 0.f;
        }
        __syncthreads();
#pragma unroll 8
        for (int k = 0; k < BK; k++) {
            float bv[4];
#pragma unroll
            for (int n = 0; n < 4; n++) bv[n] = Bs[k][ng + 32 * n];
#pragma unroll
            for (int m = 0; m < 2; m++) {
                float a = As[mg * 2 + m][k];
#pragma unroll
                for (int n = 0; n < 4; n++) acc[m][n] += a * bv[n];
            }
        }
        __syncthreads();
    }

#pragma unroll
    for (int m = 0; m < 2; m++) {
        int nn = n0 + mg * 2 + m;
        if (nn < NDIM) {
            float inv = g_inv[b * NDIM + nn];
            const float* nsr = ns + ((long)b * NDIM + nn) * HDIM;
            float* o = out + ((long)b * NDIM + nn) * HDIM;
#pragma unroll
            for (int n = 0; n < 4; n++) {
                int c = ng + 32 * n;
                o[c] = (acc[m][n] + nsr[c]) * inv;
            }
        }
    }
}

// ---------------------------------------------------------------------------
extern "C" void kernel_launch(void* const* d_in, const int* in_sizes, int n_in,
                              void* d_out, int out_size) {
    const float* node_state   = (const float*)d_in[0]; // [B,N,H]
    const float* edge_vec     = (const float*)d_in[1]; // [B,E,H]
    const float* node2edge    = (const float*)d_in[2]; // [B,E,N]
    const float* edge2node    = (const float*)d_in[3]; // [B,N,E]
    const float* edge_network = (const float*)d_in[4]; // [H,H,H]
    float* out = (float*)d_out;                        // [B,N,H]

    k_n2e  <<<dim3(63, BDIM), 256>>>(node2edge, node_state);
    k_econv<<<dim3(BDIM * EDIM / 32), 256>>>(edge_vec, edge_network);
    k_norm <<<dim3(BDIM * NDIM), 256>>>(edge2node);
    k_agg  <<<dim3(63, BDIM), 256>>>(edge2node, node_state, out);
}

// round 2
// speedup vs baseline: 1.6024x; 1.6024x over previous
#include <cuda_runtime.h>

#define BDIM 2
#define NDIM 1000
#define EDIM 2000
#define HDIM 128

#define KS_N2E 8      // K=1000 -> 8 chunks of 125
#define KS_AGG 16     // K=2000 -> 16 chunks of 125
#define KCH    125
#define BK     25

// ---------------- scratch (device globals; zero-init at module load) -------
__device__ float g_embp[(size_t)KS_N2E * BDIM * EDIM * HDIM]; // n2e partials
__device__ float g_emb [(size_t)BDIM * EDIM * HDIM];          // reduced emb
__device__ float g_new [(size_t)BDIM * EDIM * HDIM];          // econv output
__device__ float g_aggp[(size_t)KS_AGG * BDIM * NDIM * HDIM]; // agg partials
__device__ float g_inv [(size_t)BDIM * NDIM];                 // 1/(1+rowsum)

// ---------------- packed f32x2 helpers (Blackwell FFMA2) --------------------
typedef unsigned long long ull;

__device__ __forceinline__ ull fma2(ull a, ull b, ull c) {
    ull d;
    asm("fma.rn.f32x2 %0, %1, %2, %3;" : "=l"(d) : "l"(a), "l"(b), "l"(c));
    return d;
}
__device__ __forceinline__ ull pack2(float lo, float hi) {
    ull d;
    asm("mov.b64 %0, {%1, %2};" : "=l"(d) : "f"(lo), "f"(hi));
    return d;
}
__device__ __forceinline__ ull dup2(float x) { return pack2(x, x); }
__device__ __forceinline__ void unpack2(ull v, float& lo, float& hi) {
    asm("mov.b64 {%0, %1}, %2;" : "=f"(lo), "=f"(hi) : "l"(v));
}

// ---------------------------------------------------------------------------
// Generic split-K GEMM partial:
//   out[z][b][r][c] = sum_{k in chunk z} A[b][r][k] * Bm[b][k][c]
// BM=64 rows/block, 128 cols, K-chunk 125 (5 iters of BK=25).
// 256 threads: 8 warps = row groups of 8; lane -> 4 consecutive cols (float4).
// acc pairs over n (FFMA2).
// ---------------------------------------------------------------------------
__global__ void __launch_bounds__(256) k_gemm(const float* __restrict__ A,
                                              const float* __restrict__ Bm,
                                              float* __restrict__ out,
                                              int ROWS, int KTOT) {
    __shared__ float As[64][BK + 1];
    __shared__ float Bs[BK][HDIM + 4];

    int b  = blockIdx.y;
    int z  = blockIdx.z;
    int r0 = blockIdx.x * 64;
    int t  = threadIdx.x;
    int lane = t & 31;
    int mg   = t >> 5;

    const float* Ab = A  + (size_t)b * ROWS * KTOT + (size_t)z * KCH;
    const float* Bb = Bm + (size_t)b * KTOT * HDIM + (size_t)z * KCH * HDIM;

    ull acc[8][2];
#pragma unroll
    for (int q = 0; q < 8; q++) { acc[q][0] = 0ull; acc[q][1] = 0ull; }

    for (int k0 = 0; k0 < KCH; k0 += BK) {
        for (int i = t; i < 64 * BK; i += 256) {
            int m = i / BK, k = i - m * BK;
            int r = r0 + m;
            As[m][k] = (r < ROWS) ? Ab[(size_t)r * KTOT + k0 + k] : 0.f;
        }
        for (int i = t; i < BK * HDIM; i += 256) {
            int k = i >> 7, h = i & 127;
            Bs[k][h] = Bb[(size_t)(k0 + k) * HDIM + h];
        }
        __syncthreads();
#pragma unroll
        for (int k = 0; k < BK; k++) {
            float4 bv = *(const float4*)&Bs[k][lane * 4];
            ull b01 = pack2(bv.x, bv.y);
            ull b23 = pack2(bv.z, bv.w);
#pragma unroll
            for (int q = 0; q < 8; q++) {
                ull a2 = dup2(As[mg * 8 + q][k]);
                acc[q][0] = fma2(a2, b01, acc[q][0]);
                acc[q][1] = fma2(a2, b23, acc[q][1]);
            }
        }
        __syncthreads();
    }

#pragma unroll
    for (int q = 0; q < 8; q++) {
        int r = r0 + mg * 8 + q;
        if (r < ROWS) {
            float4 v;
            unpack2(acc[q][0], v.x, v.y);
            unpack2(acc[q][1], v.z, v.w);
            *(float4*)&out[((size_t)z * BDIM * ROWS + (size_t)b * ROWS + r) * HDIM
                           + lane * 4] = v;
        }
    }
}

// ---------------------------------------------------------------------------
// Reduce n2e partials: g_emb = sum_z g_embp[z]
// ---------------------------------------------------------------------------
__global__ void __launch_bounds__(256) k_red() {
    const size_t STR = (size_t)BDIM * EDIM * HDIM / 4;   // in float4
    size_t f = (size_t)blockIdx.x * 256 + threadIdx.x;   // grid covers STR
    const float4* p = (const float4*)g_embp;
    float4 s = p[f];
#pragma unroll
    for (int z = 1; z < KS_N2E; z++) {
        float4 v = p[z * STR + f];
        s.x += v.x; s.y += v.y; s.z += v.z; s.w += v.w;
    }
    ((float4*)g_emb)[f] = s;
}

// ---------------------------------------------------------------------------
// Dominant kernel (8.4 GMAC), FFMA2 version:
//   g_new[r][i] = sum_h ev[r][h] * ( sum_j EN[h,i,j] * emb[r][j] )
// 125 blocks x 32 rows. 8 warps: mg = w>>1 -> rows [mg*8, mg*8+8) paired for
// f32x2; ih = w&1 -> cols i0 = ih*64 + lane, i0+32.
// EN streamed in (h, 32-j) chunks with register-prefetch double buffering.
// emb kept transposed [j][m] so row-pairs load as aligned 64-bit LDS.
// ---------------------------------------------------------------------------
__global__ void __launch_bounds__(256) k_econv(const float* __restrict__ ev,
                                               const float* __restrict__ EN) {
    __shared__ float emb_sT[HDIM][32];       // [j][m], 16 KB
    __shared__ float en_s[HDIM][33];         // [i][j-chunk], 16.9 KB, pad 33

    int r0   = blockIdx.x * 32;
    int t    = threadIdx.x;
    int lane = t & 31;
    int w    = t >> 5;
    int mg   = w >> 1;                       // 0..3 -> rows mg*8..mg*8+7
    int ih   = w & 1;
    int i0   = ih * 64 + lane;               // cols i0, i0+32

    // fill emb transposed (strided global read; tiny one-time cost)
    for (int i = t; i < 32 * HDIM; i += 256) {
        int m = i & 31, h = i >> 5;
        emb_sT[h][m] = g_emb[(size_t)(r0 + m) * HDIM + h];
    }

    ull acc[4][2];
#pragma unroll
    for (int p = 0; p < 4; p++) { acc[p][0] = 0ull; acc[p][1] = 0ull; }
    ull tt[4][2];

    // prefetch chunk 0 (h=0, jc=0)
    float4 pf[4];
    {
        const float* ENc = EN;
#pragma unroll
        for (int k = 0; k < 4; k++) {
            int f = t + 256 * k;
            pf[k] = *(const float4*)(ENc + (f >> 3) * HDIM + (f & 7) * 4);
        }
    }

    const int NC = HDIM * 4;                 // 512 chunks
    for (int c = 0; c < NC; ++c) {
        __syncthreads();                     // readers of previous chunk done
        // store prefetched chunk to smem (conflict-free scalar STS)
#pragma unroll
        for (int k = 0; k < 4; k++) {
            int f = t + 256 * k;
            float* dst = &en_s[f >> 3][(f & 7) * 4];
            dst[0] = pf[k].x; dst[1] = pf[k].y; dst[2] = pf[k].z; dst[3] = pf[k].w;
        }
        __syncthreads();
        // issue loads for next chunk; latency hidden under compute below
        if (c + 1 < NC) {
            int hn = (c + 1) >> 2, jn = ((c + 1) & 3) * 32;
            const float* ENc = EN + (size_t)hn * (HDIM * HDIM) + jn;
#pragma unroll
            for (int k = 0; k < 4; k++) {
                int f = t + 256 * k;
                pf[k] = *(const float4*)(ENc + (f >> 3) * HDIM + (f & 7) * 4);
            }
        }

        int jcq = c & 3;
        if (jcq == 0) {
#pragma unroll
            for (int p = 0; p < 4; p++) { tt[p][0] = 0ull; tt[p][1] = 0ull; }
        }
        int jbase = jcq * 32;
#pragma unroll
        for (int j = 0; j < 32; ++j) {
            const float* er = &emb_sT[jbase + j][mg * 8];
            ulonglong2 ea = *(const ulonglong2*)er;        // rows (0,1),(2,3)
            ulonglong2 eb = *(const ulonglong2*)(er + 4);  // rows (4,5),(6,7)
            ull b0 = dup2(en_s[i0][j]);
            ull b1 = dup2(en_s[i0 + 32][j]);
            tt[0][0] = fma2(ea.x, b0, tt[0][0]); tt[0][1] = fma2(ea.x, b1, tt[0][1]);
            tt[1][0] = fma2(ea.y, b0, tt[1][0]); tt[1][1] = fma2(ea.y, b1, tt[1][1]);
            tt[2][0] = fma2(eb.x, b0, tt[2][0]); tt[2][1] = fma2(eb.x, b1, tt[2][1]);
            tt[3][0] = fma2(eb.y, b0, tt[3][0]); tt[3][1] = fma2(eb.y, b1, tt[3][1]);
        }
        if (jcq == 3) {                      // fold edge_vec weight for this h
            int h = c >> 2;
            const float* evr = ev + (size_t)(r0 + mg * 8) * HDIM + h;
#pragma unroll
            for (int p = 0; p < 4; p++) {
                ull wp = pack2(evr[(size_t)(2 * p) * HDIM],
                               evr[(size_t)(2 * p + 1) * HDIM]);
                acc[p][0] = fma2(wp, tt[p][0], acc[p][0]);
                acc[p][1] = fma2(wp, tt[p][1], acc[p][1]);
            }
        }
    }

#pragma unroll
    for (int p = 0; p < 4; p++) {
        int row = r0 + mg * 8 + 2 * p;
        float lo0, hi0, lo1, hi1;
        unpack2(acc[p][0], lo0, hi0);
        unpack2(acc[p][1], lo1, hi1);
        g_new[(size_t)row * HDIM + i0]            = lo0;
        g_new[(size_t)(row + 1) * HDIM + i0]      = hi0;
        g_new[(size_t)row * HDIM + i0 + 32]       = lo1;
        g_new[(size_t)(row + 1) * HDIM + i0 + 32] = hi1;
    }
}

// ---------------------------------------------------------------------------
// g_inv[row] = 1 / (1 + sum_e edge2node[row][e]),  row = b*N+n
// ---------------------------------------------------------------------------
__global__ void __launch_bounds__(256) k_norm(const float* __restrict__ e2n) {
    __shared__ float red[256];
    int row = blockIdx.x;
    const float* p = e2n + (size_t)row * EDIM;
    float s = 0.f;
    for (int e = threadIdx.x; e < EDIM; e += 256) s += p[e];
    red[threadIdx.x] = s;
    __syncthreads();
    for (int o = 128; o > 0; o >>= 1) {
        if (threadIdx.x < o) red[threadIdx.x] += red[threadIdx.x + o];
        __syncthreads();
    }
    if (threadIdx.x == 0) g_inv[row] = 1.f / (1.f + red[0]);
}

// ---------------------------------------------------------------------------
// out = (sum_z g_aggp[z] + node_state) * g_inv[row]
// ---------------------------------------------------------------------------
__global__ void __launch_bounds__(256) k_fin(const float* __restrict__ ns,
                                             float* __restrict__ out) {
    const size_t STR = (size_t)BDIM * NDIM * HDIM / 4;   // in float4
    size_t f = (size_t)blockIdx.x * 256 + threadIdx.x;   // grid covers STR
    const float4* p = (const float4*)g_aggp;
    float4 s = p[f];
#pragma unroll
    for (int z = 1; z < KS_AGG; z++) {
        float4 v = p[z * STR + f];
        s.x += v.x; s.y += v.y; s.z += v.z; s.w += v.w;
    }
    float4 n4 = ((const float4*)ns)[f];
    float inv = g_inv[(f * 4) >> 7];
    float4 o;
    o.x = (s.x + n4.x) * inv;
    o.y = (s.y + n4.y) * inv;
    o.z = (s.z + n4.z) * inv;
    o.w = (s.w + n4.w) * inv;
    ((float4*)out)[f] = o;
}

// ---------------------------------------------------------------------------
extern "C" void kernel_launch(void* const* d_in, const int* in_sizes, int n_in,
                              void* d_out, int out_size) {
    const float* node_state   = (const float*)d_in[0]; // [B,N,H]
    const float* edge_vec     = (const float*)d_in[1]; // [B,E,H]
    const float* node2edge    = (const float*)d_in[2]; // [B,E,N]
    const float* edge2node    = (const float*)d_in[3]; // [B,N,E]
    const float* edge_network = (const float*)d_in[4]; // [H,H,H]
    float* out = (float*)d_out;                        // [B,N,H]

    void* p_embp; cudaGetSymbolAddress(&p_embp, g_embp);
    void* p_new;  cudaGetSymbolAddress(&p_new,  g_new);
    void* p_aggp; cudaGetSymbolAddress(&p_aggp, g_aggp);

    // n2e partials: rows=E, K=N -> grid (2000/64=32, B, 8)
    k_gemm<<<dim3(32, BDIM, KS_N2E), 256>>>(node2edge, node_state,
                                            (float*)p_embp, EDIM, NDIM);
    // reduce partials -> g_emb  (B*E*H/4 = 128K float4 -> 512 blocks)
    k_red<<<512, 256>>>();
    // dominant contraction
    k_econv<<<BDIM * EDIM / 32, 256>>>(edge_vec, edge_network);
    // agg partials: rows=N, K=E -> grid (1024/64=16, B, 16)
    k_gemm<<<dim3(16, BDIM, KS_AGG), 256>>>(edge2node, (const float*)p_new,
                                            (float*)p_aggp, NDIM, EDIM);
    // norm + epilogue
    k_norm<<<BDIM * NDIM, 256>>>(edge2node);
    k_fin<<<256, 256>>>(node_state, out);    // 64K float4 / 256 = 256 blocks
}

// round 4
// speedup vs baseline: 3.5223x; 2.1982x over previous
#include <cuda_runtime.h>
#include <cuda_bf16.h>
#include <cstdint>

#define BDIM 2
#define NDIM 1000
#define EDIM 2000
#define HDIM 128
#define RTOT (BDIM * EDIM)          // 4000 flat rows

#define KS_N2E 8
#define KS_AGG 16
#define KCH    125
#define BK     25

#define HSPLIT 4                    // h-splits for tensor kernel
#define NH_PER (HDIM / HSPLIT)      // 32 h per block

// ---------------- scratch (device globals) ---------------------------------
__device__ float g_embp[(size_t)KS_N2E * RTOT * HDIM];
__device__ float g_emb [(size_t)RTOT * HDIM];
__device__ float g_new [(size_t)RTOT * HDIM];
__device__ float g_newp[(size_t)HSPLIT * RTOT * HDIM];
__device__ float g_aggp[(size_t)KS_AGG * BDIM * NDIM * HDIM];
__device__ float g_inv [(size_t)BDIM * NDIM];
// pre-split EN (bf16 hi/lo planes), plain [h][i][j] layout
__device__ unsigned short g_ENhi[(size_t)HDIM * 16384];
__device__ unsigned short g_ENlo[(size_t)HDIM * 16384];

// ---------------- f32x2 helpers (scalar GEMMs) ------------------------------
typedef unsigned long long ull;
__device__ __forceinline__ ull fma2(ull a, ull b, ull c) {
    ull d; asm("fma.rn.f32x2 %0, %1, %2, %3;" : "=l"(d) : "l"(a), "l"(b), "l"(c));
    return d;
}
__device__ __forceinline__ ull pack2(float lo, float hi) {
    ull d; asm("mov.b64 %0, {%1, %2};" : "=l"(d) : "f"(lo), "f"(hi)); return d;
}
__device__ __forceinline__ ull dup2(float x) { return pack2(x, x); }
__device__ __forceinline__ void unpack2(ull v, float& lo, float& hi) {
    asm("mov.b64 {%0, %1}, %2;" : "=f"(lo), "=f"(hi) : "l"(v));
}

// ---------------- mma.sync helpers ------------------------------------------
__device__ __forceinline__ uint32_t smem_u32(const void* p) {
    uint32_t a;
    asm("{ .reg .u64 t; cvta.to.shared.u64 t, %1; cvt.u32.u64 %0, t; }"
        : "=r"(a) : "l"(p));
    return a;
}
__device__ __forceinline__ void ldsm4(uint32_t* r, uint32_t addr) {
    asm volatile("ldmatrix.sync.aligned.m8n8.x4.shared.b16 {%0,%1,%2,%3}, [%4];"
                 : "=r"(r[0]), "=r"(r[1]), "=r"(r[2]), "=r"(r[3]) : "r"(addr));
}
__device__ __forceinline__ void mma_bf16(float* d, const uint32_t* a,
                                         uint32_t b0, uint32_t b1) {
    asm volatile("mma.sync.aligned.m16n8k16.row.col.f32.bf16.bf16.f32 "
                 "{%0,%1,%2,%3}, {%4,%5,%6,%7}, {%8,%9}, {%0,%1,%2,%3};"
                 : "+f"(d[0]), "+f"(d[1]), "+f"(d[2]), "+f"(d[3])
                 : "r"(a[0]), "r"(a[1]), "r"(a[2]), "r"(a[3]), "r"(b0), "r"(b1));
}
__device__ __forceinline__ uint32_t cvt2(float lo, float hi) {
    uint32_t r;
    asm("cvt.rn.satfinite.bf16x2.f32 %0, %1, %2;" : "=r"(r) : "f"(hi), "f"(lo));
    return r;
}

// ---------------------------------------------------------------------------
// Split-K scalar GEMM (proven in r2; handles n2e and agg)
// ---------------------------------------------------------------------------
__global__ void __launch_bounds__(256) k_gemm(const float* __restrict__ A,
                                              const float* __restrict__ Bm,
                                              float* __restrict__ out,
                                              int ROWS, int KTOT) {
    __shared__ float As[64][BK + 1];
    __shared__ float Bs[BK][HDIM + 4];

    int b  = blockIdx.y;
    int z  = blockIdx.z;
    int r0 = blockIdx.x * 64;
    int t  = threadIdx.x;
    int lane = t & 31;
    int mg   = t >> 5;

    const float* Ab = A  + (size_t)b * ROWS * KTOT + (size_t)z * KCH;
    const float* Bb = Bm + (size_t)b * KTOT * HDIM + (size_t)z * KCH * HDIM;

    ull acc[8][2];
#pragma unroll
    for (int q = 0; q < 8; q++) { acc[q][0] = 0ull; acc[q][1] = 0ull; }

    for (int k0 = 0; k0 < KCH; k0 += BK) {
        for (int i = t; i < 64 * BK; i += 256) {
            int m = i / BK, k = i - m * BK;
            int r = r0 + m;
            As[m][k] = (r < ROWS) ? Ab[(size_t)r * KTOT + k0 + k] : 0.f;
        }
        for (int i = t; i < BK * HDIM; i += 256) {
            int k = i >> 7, h = i & 127;
            Bs[k][h] = Bb[(size_t)(k0 + k) * HDIM + h];
        }
        __syncthreads();
#pragma unroll
        for (int k = 0; k < BK; k++) {
            float4 bv = *(const float4*)&Bs[k][lane * 4];
            ull b01 = pack2(bv.x, bv.y);
            ull b23 = pack2(bv.z, bv.w);
#pragma unroll
            for (int q = 0; q < 8; q++) {
                ull a2 = dup2(As[mg * 8 + q][k]);
                acc[q][0] = fma2(a2, b01, acc[q][0]);
                acc[q][1] = fma2(a2, b23, acc[q][1]);
            }
        }
        __syncthreads();
    }

#pragma unroll
    for (int q = 0; q < 8; q++) {
        int r = r0 + mg * 8 + q;
        if (r < ROWS) {
            float4 v;
            unpack2(acc[q][0], v.x, v.y);
            unpack2(acc[q][1], v.z, v.w);
            *(float4*)&out[((size_t)z * BDIM * ROWS + (size_t)b * ROWS + r) * HDIM
                           + lane * 4] = v;
        }
    }
}

__global__ void __launch_bounds__(256) k_red() {
    const size_t STR = (size_t)RTOT * HDIM / 4;
    size_t f = (size_t)blockIdx.x * 256 + threadIdx.x;
    const float4* p = (const float4*)g_embp;
    float4 s = p[f];
#pragma unroll
    for (int z = 1; z < KS_N2E; z++) {
        float4 v = p[z * STR + f];
        s.x += v.x; s.y += v.y; s.z += v.z; s.w += v.w;
    }
    ((float4*)g_emb)[f] = s;
}

// ---------------------------------------------------------------------------
// Prep: split EN into bf16 hi/lo planes, plain [h][i][j]
// ---------------------------------------------------------------------------
__global__ void __launch_bounds__(256) k_prep(const float* __restrict__ EN) {
    int h = blockIdx.x;
    int t = threadIdx.x;
    const float* src = EN + (size_t)h * 16384;
    unsigned short* dh = g_ENhi + (size_t)h * 16384;
    unsigned short* dl = g_ENlo + (size_t)h * 16384;
    for (int idx = t; idx < 16384; idx += 256) {
        float v = src[idx];
        __nv_bfloat16 hb = __float2bfloat16(v);
        float hf = __bfloat162float(hb);
        __nv_bfloat16 lb = __float2bfloat16(v - hf);
        dh[idx] = *(unsigned short*)&hb;
        dl[idx] = *(unsigned short*)&lb;
    }
}

// ---------------------------------------------------------------------------
// Tensor-core econv via mma.sync (bf16, 3-term split):
//   newp[hs][r][i] = sum_{h in split} sum_j (ev[r,h]*emb[r,j]) * EN[h,i,j]
// grid (32 M-tiles, HSPLIT), 256 threads = 8 warps.
// Warp w: rows (w&3)*32..+31, cols (w>>2)*64..+63 of the 128x128 tile.
// smem tiles padded to 272B rows -> conflict-free ldmatrix.
// ---------------------------------------------------------------------------
#define ASTRB 272u                   // (128+8) bf16 = 272 bytes per row
#define OFF_AH 0u
#define OFF_AL 34816u
#define OFF_BH 69632u
#define OFF_BL 104448u
#define OFF_EMB 139264u              // float [128][132]
#define OFF_EV  206848u              // float [NH_PER][128]
#define SM_ECONV 223232u

__global__ void __launch_bounds__(256) k_econv_tc(const float* __restrict__ ev,
                                                  const unsigned short* __restrict__ ENhi,
                                                  const unsigned short* __restrict__ ENlo,
                                                  float* __restrict__ newp) {
    extern __shared__ char smraw[];
    uint32_t base32 = smem_u32(smraw);
    float* embs = (float*)(smraw + OFF_EMB);   // [128][132]
    float* evs  = (float*)(smraw + OFF_EV);    // [NH_PER][128]

    int t = threadIdx.x;
    int lane = t & 31, w = t >> 5;
    int r0 = blockIdx.x * 128;
    int hbase = blockIdx.y * NH_PER;

    // stage emb (fp32) + ev slice
    for (int idx = t; idx < 128 * 128; idx += 256) {
        int m = idx >> 7, j = idx & 127;
        int r = r0 + m;
        embs[m * 132 + j] = (r < RTOT) ? g_emb[(size_t)r * HDIM + j] : 0.f;
    }
    for (int idx = t; idx < NH_PER * 128; idx += 256) {
        int hh = idx >> 7, m = idx & 127;
        int r = r0 + m;
        evs[hh * 128 + m] = (r < RTOT) ? ev[(size_t)r * HDIM + hbase + hh] : 0.f;
    }

    float acc[2][8][4];
#pragma unroll
    for (int ms = 0; ms < 2; ms++)
#pragma unroll
        for (int nt = 0; nt < 8; nt++)
#pragma unroll
            for (int q = 0; q < 4; q++) acc[ms][nt][q] = 0.f;

    int warpM = (w & 3) * 32;
    int warpN = (w >> 2) * 64;
    // ldmatrix per-lane address offsets (bytes)
    uint32_t aoff = (uint32_t)(warpM + (lane & 15)) * ASTRB + (uint32_t)(lane >> 4) * 16u;
    uint32_t boff = (uint32_t)(warpN + ((lane >> 4) & 1) * 8 + (lane & 7)) * ASTRB
                  + (uint32_t)((lane >> 3) & 1) * 16u;

    for (int hh = 0; hh < NH_PER; hh++) {
        __syncthreads();              // prior iteration's reads complete
        // ---- copy B planes (32KB each) into padded smem ----
        {
            const uint4* sH = (const uint4*)(ENhi + (size_t)(hbase + hh) * 16384);
            const uint4* sL = (const uint4*)(ENlo + (size_t)(hbase + hh) * 16384);
#pragma unroll
            for (int k = 0; k < 8; k++) {
                int f = t + 256 * k;
                int i = f >> 4, seg = f & 15;
                uint4 vH = sH[f], vL = sL[f];
                *(uint4*)(smraw + OFF_BH + (uint32_t)i * ASTRB + seg * 16) = vH;
                *(uint4*)(smraw + OFF_BL + (uint32_t)i * ASTRB + seg * 16) = vL;
            }
        }
        // ---- build A planes: P = ev*emb, hi/lo bf16 ----
        {
#pragma unroll
            for (int k = 0; k < 32; k++) {
                int p = t + 256 * k;              // pair index 0..8191
                int m = p >> 6, jp = p & 63;
                float evv = evs[hh * 128 + m];
                float2 e = *(const float2*)&embs[m * 132 + jp * 2];
                float p0 = e.x * evv, p1 = e.y * evv;
                uint32_t hp = cvt2(p0, p1);
                float h0 = __uint_as_float(hp << 16);
                float h1 = __uint_as_float(hp & 0xFFFF0000u);
                uint32_t lp = cvt2(p0 - h0, p1 - h1);
                *(uint32_t*)(smraw + OFF_AH + (uint32_t)m * ASTRB + jp * 4) = hp;
                *(uint32_t*)(smraw + OFF_AL + (uint32_t)m * ASTRB + jp * 4) = lp;
            }
        }
        __syncthreads();

        // ---- 3 terms: (AH,BH), (AH,BL), (AL,BH) ----
#pragma unroll
        for (int term = 0; term < 3; term++) {
            uint32_t Ab = base32 + ((term == 2) ? OFF_AL : OFF_AH) + aoff;
            uint32_t Bb = base32 + ((term == 1) ? OFF_BL : OFF_BH) + boff;
#pragma unroll
            for (int ks = 0; ks < 8; ks++) {
                uint32_t a0[4], a1[4];
                ldsm4(a0, Ab + ks * 32u);
                ldsm4(a1, Ab + 4352u + ks * 32u);      // msub=1: +16 rows
                uint32_t bf[4][4];
#pragma unroll
                for (int np = 0; np < 4; np++)
                    ldsm4(bf[np], Bb + (uint32_t)np * 4352u + ks * 32u);
#pragma unroll
                for (int nt = 0; nt < 8; nt++) {
                    uint32_t b0 = bf[nt >> 1][(nt & 1) * 2];
                    uint32_t b1 = bf[nt >> 1][(nt & 1) * 2 + 1];
                    mma_bf16(acc[0][nt], a0, b0, b1);
                    mma_bf16(acc[1][nt], a1, b0, b1);
                }
            }
        }
    }

    // ---- epilogue: write 32x64 warp patch to partial buffer ----
    size_t obase = (size_t)blockIdx.y * RTOT * HDIM;
#pragma unroll
    for (int ms = 0; ms < 2; ms++) {
        int rA = r0 + warpM + ms * 16 + (lane >> 2);
        int rB = rA + 8;
#pragma unroll
        for (int nt = 0; nt < 8; nt++) {
            int col = warpN + nt * 8 + (lane & 3) * 2;
            if (rA < RTOT)
                *(float2*)&newp[obase + (size_t)rA * HDIM + col] =
                    make_float2(acc[ms][nt][0], acc[ms][nt][1]);
            if (rB < RTOT)
                *(float2*)&newp[obase + (size_t)rB * HDIM + col] =
                    make_float2(acc[ms][nt][2], acc[ms][nt][3]);
        }
    }
}

// g_new = sum over HSPLIT partials
__global__ void __launch_bounds__(256) k_nred(const float* __restrict__ newp) {
    const size_t STR = (size_t)RTOT * HDIM / 4;
    size_t f = (size_t)blockIdx.x * 256 + threadIdx.x;
    const float4* p = (const float4*)newp;
    float4 s = p[f];
#pragma unroll
    for (int z = 1; z < HSPLIT; z++) {
        float4 v = p[z * STR + f];
        s.x += v.x; s.y += v.y; s.z += v.z; s.w += v.w;
    }
    ((float4*)g_new)[f] = s;
}

__global__ void __launch_bounds__(256) k_norm(const float* __restrict__ e2n) {
    __shared__ float red[256];
    int row = blockIdx.x;
    const float* p = e2n + (size_t)row * EDIM;
    float s = 0.f;
    for (int e = threadIdx.x; e < EDIM; e += 256) s += p[e];
    red[threadIdx.x] = s;
    __syncthreads();
    for (int o = 128; o > 0; o >>= 1) {
        if (threadIdx.x < o) red[threadIdx.x] += red[threadIdx.x + o];
        __syncthreads();
    }
    if (threadIdx.x == 0) g_inv[row] = 1.f / (1.f + red[0]);
}

__global__ void __launch_bounds__(256) k_fin(const float* __restrict__ ns,
                                             float* __restrict__ out) {
    const size_t STR = (size_t)BDIM * NDIM * HDIM / 4;
    size_t f = (size_t)blockIdx.x * 256 + threadIdx.x;
    const float4* p = (const float4*)g_aggp;
    float4 s = p[f];
#pragma unroll
    for (int z = 1; z < KS_AGG; z++) {
        float4 v = p[z * STR + f];
        s.x += v.x; s.y += v.y; s.z += v.z; s.w += v.w;
    }
    float4 n4 = ((const float4*)ns)[f];
    float inv = g_inv[(f * 4) >> 7];
    float4 o;
    o.x = (s.x + n4.x) * inv;
    o.y = (s.y + n4.y) * inv;
    o.z = (s.z + n4.z) * inv;
    o.w = (s.w + n4.w) * inv;
    ((float4*)out)[f] = o;
}

// ---------------------------------------------------------------------------
extern "C" void kernel_launch(void* const* d_in, const int* in_sizes, int n_in,
                              void* d_out, int out_size) {
    const float* node_state   = (const float*)d_in[0];
    const float* edge_vec     = (const float*)d_in[1];
    const float* node2edge    = (const float*)d_in[2];
    const float* edge2node    = (const float*)d_in[3];
    const float* edge_network = (const float*)d_in[4];
    float* out = (float*)d_out;

    void* p_embp; cudaGetSymbolAddress(&p_embp, g_embp);
    void* p_new;  cudaGetSymbolAddress(&p_new,  g_new);
    void* p_newp; cudaGetSymbolAddress(&p_newp, g_newp);
    void* p_aggp; cudaGetSymbolAddress(&p_aggp, g_aggp);
    void* p_enh;  cudaGetSymbolAddress(&p_enh,  g_ENhi);
    void* p_enl;  cudaGetSymbolAddress(&p_enl,  g_ENlo);

    cudaFuncSetAttribute(k_econv_tc, cudaFuncAttributeMaxDynamicSharedMemorySize,
                         SM_ECONV);

    k_gemm<<<dim3(32, BDIM, KS_N2E), 256>>>(node2edge, node_state,
                                            (float*)p_embp, EDIM, NDIM);
    k_red<<<512, 256>>>();
    k_prep<<<HDIM, 256>>>(edge_network);
    k_econv_tc<<<dim3(32, HSPLIT), 256, SM_ECONV>>>(edge_vec,
                                                    (const unsigned short*)p_enh,
                                                    (const unsigned short*)p_enl,
                                                    (float*)p_newp);
    k_nred<<<500, 256>>>((const float*)p_newp);
    k_gemm<<<dim3(16, BDIM, KS_AGG), 256>>>(edge2node, (const float*)p_new,
                                            (float*)p_aggp, NDIM, EDIM);
    k_norm<<<BDIM * NDIM, 256>>>(edge2node);
    k_fin<<<256, 256>>>(node_state, out);
}

// round 5
// speedup vs baseline: 4.2592x; 1.2092x over previous
#include <cuda_runtime.h>
#include <cuda_bf16.h>
#include <cstdint>

#define BDIM 2
#define NDIM 1000
#define EDIM 2000
#define HDIM 128
#define RTOT (BDIM * EDIM)          // 4000 flat rows

#define KS_N2E 8
#define KS_AGG 16
#define KCH    125
#define BK     25

#define HSPLIT 4                    // h-splits for tensor kernel
#define NH_PER (HDIM / HSPLIT)      // 32 h per block

// ---------------- scratch (device globals) ---------------------------------
__device__ float g_embp[(size_t)KS_N2E * RTOT * HDIM];
__device__ float g_emb [(size_t)RTOT * HDIM];
__device__ float g_new [(size_t)RTOT * HDIM];
__device__ float g_newp[(size_t)HSPLIT * RTOT * HDIM];
__device__ float g_aggp[(size_t)KS_AGG * BDIM * NDIM * HDIM];
__device__ float g_inv [(size_t)BDIM * NDIM];
// pre-split EN (bf16 hi/lo planes), plain [h][i][j] layout
__device__ unsigned short g_ENhi[(size_t)HDIM * 16384];
__device__ unsigned short g_ENlo[(size_t)HDIM * 16384];

// ---------------- f32x2 helpers (scalar GEMMs) ------------------------------
typedef unsigned long long ull;
__device__ __forceinline__ ull fma2(ull a, ull b, ull c) {
    ull d; asm("fma.rn.f32x2 %0, %1, %2, %3;" : "=l"(d) : "l"(a), "l"(b), "l"(c));
    return d;
}
__device__ __forceinline__ ull pack2(float lo, float hi) {
    ull d; asm("mov.b64 %0, {%1, %2};" : "=l"(d) : "f"(lo), "f"(hi)); return d;
}
__device__ __forceinline__ ull dup2(float x) { return pack2(x, x); }
__device__ __forceinline__ void unpack2(ull v, float& lo, float& hi) {
    asm("mov.b64 {%0, %1}, %2;" : "=f"(lo), "=f"(hi) : "l"(v));
}

// ---------------- mma.sync / cp.async helpers --------------------------------
__device__ __forceinline__ uint32_t smem_u32(const void* p) {
    uint32_t a;
    asm("{ .reg .u64 t; cvta.to.shared.u64 t, %1; cvt.u32.u64 %0, t; }"
        : "=r"(a) : "l"(p));
    return a;
}
__device__ __forceinline__ void ldsm4(uint32_t* r, uint32_t addr) {
    asm volatile("ldmatrix.sync.aligned.m8n8.x4.shared.b16 {%0,%1,%2,%3}, [%4];"
                 : "=r"(r[0]), "=r"(r[1]), "=r"(r[2]), "=r"(r[3]) : "r"(addr));
}
__device__ __forceinline__ void mma_bf16(float* d, const uint32_t* a,
                                         uint32_t b0, uint32_t b1) {
    asm volatile("mma.sync.aligned.m16n8k16.row.col.f32.bf16.bf16.f32 "
                 "{%0,%1,%2,%3}, {%4,%5,%6,%7}, {%8,%9}, {%0,%1,%2,%3};"
                 : "+f"(d[0]), "+f"(d[1]), "+f"(d[2]), "+f"(d[3])
                 : "r"(a[0]), "r"(a[1]), "r"(a[2]), "r"(a[3]), "r"(b0), "r"(b1));
}
__device__ __forceinline__ uint32_t cvt2(float lo, float hi) {
    uint32_t r;
    asm("cvt.rn.satfinite.bf16x2.f32 %0, %1, %2;" : "=r"(r) : "f"(hi), "f"(lo));
    return r;
}
__device__ __forceinline__ void cp16(uint32_t dst, const void* src) {
    asm volatile("cp.async.cg.shared.global [%0], [%1], 16;"
                 :: "r"(dst), "l"(src) : "memory");
}
__device__ __forceinline__ void cp_commit() {
    asm volatile("cp.async.commit_group;" ::: "memory");
}
__device__ __forceinline__ void cp_wait0() {
    asm volatile("cp.async.wait_group 0;" ::: "memory");
}

// ---------------------------------------------------------------------------
// Split-K scalar GEMM (proven; handles n2e and agg)
// ---------------------------------------------------------------------------
__global__ void __launch_bounds__(256) k_gemm(const float* __restrict__ A,
                                              const float* __restrict__ Bm,
                                              float* __restrict__ out,
                                              int ROWS, int KTOT) {
    __shared__ float As[64][BK + 1];
    __shared__ float Bs[BK][HDIM + 4];

    int b  = blockIdx.y;
    int z  = blockIdx.z;
    int r0 = blockIdx.x * 64;
    int t  = threadIdx.x;
    int lane = t & 31;
    int mg   = t >> 5;

    const float* Ab = A  + (size_t)b * ROWS * KTOT + (size_t)z * KCH;
    const float* Bb = Bm + (size_t)b * KTOT * HDIM + (size_t)z * KCH * HDIM;

    ull acc[8][2];
#pragma unroll
    for (int q = 0; q < 8; q++) { acc[q][0] = 0ull; acc[q][1] = 0ull; }

    for (int k0 = 0; k0 < KCH; k0 += BK) {
        for (int i = t; i < 64 * BK; i += 256) {
            int m = i / BK, k = i - m * BK;
            int r = r0 + m;
            As[m][k] = (r < ROWS) ? Ab[(size_t)r * KTOT + k0 + k] : 0.f;
        }
        for (int i = t; i < BK * HDIM; i += 256) {
            int k = i >> 7, h = i & 127;
            Bs[k][h] = Bb[(size_t)(k0 + k) * HDIM + h];
        }
        __syncthreads();
#pragma unroll
        for (int k = 0; k < BK; k++) {
            float4 bv = *(const float4*)&Bs[k][lane * 4];
            ull b01 = pack2(bv.x, bv.y);
            ull b23 = pack2(bv.z, bv.w);
#pragma unroll
            for (int q = 0; q < 8; q++) {
                ull a2 = dup2(As[mg * 8 + q][k]);
                acc[q][0] = fma2(a2, b01, acc[q][0]);
                acc[q][1] = fma2(a2, b23, acc[q][1]);
            }
        }
        __syncthreads();
    }

#pragma unroll
    for (int q = 0; q < 8; q++) {
        int r = r0 + mg * 8 + q;
        if (r < ROWS) {
            float4 v;
            unpack2(acc[q][0], v.x, v.y);
            unpack2(acc[q][1], v.z, v.w);
            *(float4*)&out[((size_t)z * BDIM * ROWS + (size_t)b * ROWS + r) * HDIM
                           + lane * 4] = v;
        }
    }
}

__global__ void __launch_bounds__(256) k_red() {
    const size_t STR = (size_t)RTOT * HDIM / 4;
    size_t f = (size_t)blockIdx.x * 256 + threadIdx.x;
    const float4* p = (const float4*)g_embp;
    float4 s = p[f];
#pragma unroll
    for (int z = 1; z < KS_N2E; z++) {
        float4 v = p[z * STR + f];
        s.x += v.x; s.y += v.y; s.z += v.z; s.w += v.w;
    }
    ((float4*)g_emb)[f] = s;
}

// ---------------------------------------------------------------------------
// Prep: split EN into bf16 hi/lo planes, plain [h][i][j]
// ---------------------------------------------------------------------------
__global__ void __launch_bounds__(256) k_prep(const float* __restrict__ EN) {
    int h = blockIdx.x;
    int t = threadIdx.x;
    const float* src = EN + (size_t)h * 16384;
    unsigned short* dh = g_ENhi + (size_t)h * 16384;
    unsigned short* dl = g_ENlo + (size_t)h * 16384;
    for (int idx = t; idx < 16384; idx += 256) {
        float v = src[idx];
        __nv_bfloat16 hb = __float2bfloat16(v);
        float hf = __bfloat162float(hb);
        __nv_bfloat16 lb = __float2bfloat16(v - hf);
        dh[idx] = *(unsigned short*)&hb;
        dl[idx] = *(unsigned short*)&lb;
    }
}

// ---------------------------------------------------------------------------
// Tensor-core econv via mma.sync, STATIC A + cp.async pipelined B:
//   tt = emb_tile @ EN_h^T (3-term bf16 split), acc += ev[r,h] * tt
// grid (32 M-tiles, HSPLIT), 256 threads = 8 warps.
// Warp w: rows (w&3)*32..+31, cols (w>>2)*64..+63 of the 128x128 tile.
// smem rows padded to 272B -> conflict-free ldmatrix.
// ---------------------------------------------------------------------------
#define ASTRB 272u
#define PLANE 34816u                 // 128 * 272
#define OFF_AH 0u
#define OFF_AL 34816u
#define OFF_B  69632u                // stage s at OFF_B + s*69632 (BH, then BL)
#define OFF_EV 208896u               // float [NH_PER][128]
#define SM_ECONV 225280u

__global__ void __launch_bounds__(256) k_econv_tc(const float* __restrict__ ev,
                                                  const unsigned short* __restrict__ ENhi,
                                                  const unsigned short* __restrict__ ENlo,
                                                  float* __restrict__ newp) {
    extern __shared__ char smraw[];
    uint32_t base32 = smem_u32(smraw);
    float* evs = (float*)(smraw + OFF_EV);

    int t = threadIdx.x;
    int lane = t & 31, w = t >> 5;
    int r0 = blockIdx.x * 128;
    int hbase = blockIdx.y * NH_PER;

    // ---- issue stage-0 B copy immediately (overlaps A build) ----
    {
        const char* sH = (const char*)(ENhi + (size_t)hbase * 16384);
        const char* sL = (const char*)(ENlo + (size_t)hbase * 16384);
        uint32_t dst = base32 + OFF_B;
#pragma unroll
        for (int k = 0; k < 8; k++) {
            int f = t + 256 * k;
            uint32_t i = (uint32_t)(f >> 4), seg = (uint32_t)(f & 15);
            uint32_t o = i * ASTRB + seg * 16u;
            cp16(dst + o,          sH + (size_t)f * 16);
            cp16(dst + PLANE + o,  sL + (size_t)f * 16);
        }
        cp_commit();
    }

    // ---- build static A (emb hi/lo bf16), straight from gmem ----
#pragma unroll 4
    for (int k = 0; k < 32; k++) {
        int p = t + 256 * k;                 // pair index 0..8191
        int m = p >> 6, jp = p & 63;
        int r = r0 + m;
        float2 e = (r < RTOT) ? *(const float2*)&g_emb[(size_t)r * HDIM + jp * 2]
                              : make_float2(0.f, 0.f);
        uint32_t hp = cvt2(e.x, e.y);
        float h0 = __uint_as_float(hp << 16);
        float h1 = __uint_as_float(hp & 0xFFFF0000u);
        uint32_t lp = cvt2(e.x - h0, e.y - h1);
        *(uint32_t*)(smraw + OFF_AH + (uint32_t)m * ASTRB + jp * 4) = hp;
        *(uint32_t*)(smraw + OFF_AL + (uint32_t)m * ASTRB + jp * 4) = lp;
    }
    // ---- stage ev slice ----
    for (int idx = t; idx < NH_PER * 128; idx += 256) {
        int hh = idx >> 7, m = idx & 127;
        int r = r0 + m;
        evs[hh * 128 + m] = (r < RTOT) ? ev[(size_t)r * HDIM + hbase + hh] : 0.f;
    }

    float acc[2][8][4];
#pragma unroll
    for (int ms = 0; ms < 2; ms++)
#pragma unroll
        for (int nt = 0; nt < 8; nt++)
#pragma unroll
            for (int q = 0; q < 4; q++) acc[ms][nt][q] = 0.f;

    int warpM = (w & 3) * 32;
    int warpN = (w >> 2) * 64;
    uint32_t aoff = (uint32_t)(warpM + (lane & 15)) * ASTRB + (uint32_t)(lane >> 4) * 16u;
    uint32_t boff = (uint32_t)(warpN + ((lane >> 4) & 1) * 8 + (lane & 7)) * ASTRB
                  + (uint32_t)((lane >> 3) & 1) * 16u;
    uint32_t AbH = base32 + OFF_AH + aoff;
    uint32_t AbL = base32 + OFF_AL + aoff;

    // row-local indices for the ev epilogue
    int rl0 = warpM + (lane >> 2);           // ms=0 upper
    // ms row offsets: ms*16; +8 for the second accum pair

    for (int hh = 0; hh < NH_PER; hh++) {
        int s = hh & 1;
        cp_wait0();                          // stage s copy complete (this thread)
        __syncthreads();                     // visible to all; all readers of 1-s done

        if (hh + 1 < NH_PER) {               // issue stage 1-s for h+1
            const char* sH = (const char*)(ENhi + (size_t)(hbase + hh + 1) * 16384);
            const char* sL = (const char*)(ENlo + (size_t)(hbase + hh + 1) * 16384);
            uint32_t dst = base32 + OFF_B + (uint32_t)(1 - s) * 69632u;
#pragma unroll
            for (int k = 0; k < 8; k++) {
                int f = t + 256 * k;
                uint32_t i = (uint32_t)(f >> 4), seg = (uint32_t)(f & 15);
                uint32_t o = i * ASTRB + seg * 16u;
                cp16(dst + o,         sH + (size_t)f * 16);
                cp16(dst + PLANE + o, sL + (size_t)f * 16);
            }
            cp_commit();
        }

        uint32_t BbH = base32 + OFF_B + (uint32_t)s * 69632u + boff;
        uint32_t BbL = BbH + PLANE;

        float tt[2][8][4];
#pragma unroll
        for (int ms = 0; ms < 2; ms++)
#pragma unroll
            for (int nt = 0; nt < 8; nt++)
#pragma unroll
                for (int q = 0; q < 4; q++) tt[ms][nt][q] = 0.f;

#pragma unroll
        for (int ks = 0; ks < 8; ks++) {
            uint32_t ah0[4], ah1[4], al0[4], al1[4];
            ldsm4(ah0, AbH + ks * 32u);
            ldsm4(ah1, AbH + 4352u + ks * 32u);
            ldsm4(al0, AbL + ks * 32u);
            ldsm4(al1, AbL + 4352u + ks * 32u);
            uint32_t bh[4][4], bl[4][4];
#pragma unroll
            for (int np = 0; np < 4; np++) {
                ldsm4(bh[np], BbH + (uint32_t)np * 4352u + ks * 32u);
                ldsm4(bl[np], BbL + (uint32_t)np * 4352u + ks * 32u);
            }
#pragma unroll
            for (int nt = 0; nt < 8; nt++) {
                uint32_t b0h = bh[nt >> 1][(nt & 1) * 2];
                uint32_t b1h = bh[nt >> 1][(nt & 1) * 2 + 1];
                uint32_t b0l = bl[nt >> 1][(nt & 1) * 2];
                uint32_t b1l = bl[nt >> 1][(nt & 1) * 2 + 1];
                mma_bf16(tt[0][nt], ah0, b0h, b1h);   // AH*BH
                mma_bf16(tt[1][nt], ah1, b0h, b1h);
                mma_bf16(tt[0][nt], ah0, b0l, b1l);   // AH*BL
                mma_bf16(tt[1][nt], ah1, b0l, b1l);
                mma_bf16(tt[0][nt], al0, b0h, b1h);   // AL*BH
                mma_bf16(tt[1][nt], al1, b0h, b1h);
            }
        }

        // ---- fold ev[r,h]: acc += ev * tt ----
        const float* evh = evs + hh * 128;
        float ev0A = evh[rl0];            // ms=0, rows rl0
        float ev0B = evh[rl0 + 8];        // ms=0, rows rl0+8
        float ev1A = evh[rl0 + 16];       // ms=1
        float ev1B = evh[rl0 + 24];
#pragma unroll
        for (int nt = 0; nt < 8; nt++) {
            acc[0][nt][0] += ev0A * tt[0][nt][0];
            acc[0][nt][1] += ev0A * tt[0][nt][1];
            acc[0][nt][2] += ev0B * tt[0][nt][2];
            acc[0][nt][3] += ev0B * tt[0][nt][3];
            acc[1][nt][0] += ev1A * tt[1][nt][0];
            acc[1][nt][1] += ev1A * tt[1][nt][1];
            acc[1][nt][2] += ev1B * tt[1][nt][2];
            acc[1][nt][3] += ev1B * tt[1][nt][3];
        }
    }

    // ---- epilogue: write 32x64 warp patch to partial buffer ----
    size_t obase = (size_t)blockIdx.y * RTOT * HDIM;
#pragma unroll
    for (int ms = 0; ms < 2; ms++) {
        int rA = r0 + warpM + ms * 16 + (lane >> 2);
        int rB = rA + 8;
#pragma unroll
        for (int nt = 0; nt < 8; nt++) {
            int col = warpN + nt * 8 + (lane & 3) * 2;
            if (rA < RTOT)
                *(float2*)&newp[obase + (size_t)rA * HDIM + col] =
                    make_float2(acc[ms][nt][0], acc[ms][nt][1]);
            if (rB < RTOT)
                *(float2*)&newp[obase + (size_t)rB * HDIM + col] =
                    make_float2(acc[ms][nt][2], acc[ms][nt][3]);
        }
    }
}

// g_new = sum over HSPLIT partials
__global__ void __launch_bounds__(256) k_nred(const float* __restrict__ newp) {
    const size_t STR = (size_t)RTOT * HDIM / 4;
    size_t f = (size_t)blockIdx.x * 256 + threadIdx.x;
    const float4* p = (const float4*)newp;
    float4 s = p[f];
#pragma unroll
    for (int z = 1; z < HSPLIT; z++) {
        float4 v = p[z * STR + f];
        s.x += v.x; s.y += v.y; s.z += v.z; s.w += v.w;
    }
    ((float4*)g_new)[f] = s;
}

__global__ void __launch_bounds__(256) k_norm(const float* __restrict__ e2n) {
    __shared__ float red[256];
    int row = blockIdx.x;
    const float* p = e2n + (size_t)row * EDIM;
    float s = 0.f;
    for (int e = threadIdx.x; e < EDIM; e += 256) s += p[e];
    red[threadIdx.x] = s;
    __syncthreads();
    for (int o = 128; o > 0; o >>= 1) {
        if (threadIdx.x < o) red[threadIdx.x] += red[threadIdx.x + o];
        __syncthreads();
    }
    if (threadIdx.x == 0) g_inv[row] = 1.f / (1.f + red[0]);
}

__global__ void __launch_bounds__(256) k_fin(const float* __restrict__ ns,
                                             float* __restrict__ out) {
    const size_t STR = (size_t)BDIM * NDIM * HDIM / 4;
    size_t f = (size_t)blockIdx.x * 256 + threadIdx.x;
    const float4* p = (const float4*)g_aggp;
    float4 s = p[f];
#pragma unroll
    for (int z = 1; z < KS_AGG; z++) {
        float4 v = p[z * STR + f];
        s.x += v.x; s.y += v.y; s.z += v.z; s.w += v.w;
    }
    float4 n4 = ((const float4*)ns)[f];
    float inv = g_inv[(f * 4) >> 7];
    float4 o;
    o.x = (s.x + n4.x) * inv;
    o.y = (s.y + n4.y) * inv;
    o.z = (s.z + n4.z) * inv;
    o.w = (s.w + n4.w) * inv;
    ((float4*)out)[f] = o;
}

// ---------------------------------------------------------------------------
extern "C" void kernel_launch(void* const* d_in, const int* in_sizes, int n_in,
                              void* d_out, int out_size) {
    const float* node_state   = (const float*)d_in[0];
    const float* edge_vec     = (const float*)d_in[1];
    const float* node2edge    = (const float*)d_in[2];
    const float* edge2node    = (const float*)d_in[3];
    const float* edge_network = (const float*)d_in[4];
    float* out = (float*)d_out;

    void* p_embp; cudaGetSymbolAddress(&p_embp, g_embp);
    void* p_new;  cudaGetSymbolAddress(&p_new,  g_new);
    void* p_newp; cudaGetSymbolAddress(&p_newp, g_newp);
    void* p_aggp; cudaGetSymbolAddress(&p_aggp, g_aggp);
    void* p_enh;  cudaGetSymbolAddress(&p_enh,  g_ENhi);
    void* p_enl;  cudaGetSymbolAddress(&p_enl,  g_ENlo);

    cudaFuncSetAttribute(k_econv_tc, cudaFuncAttributeMaxDynamicSharedMemorySize,
                         SM_ECONV);

    k_gemm<<<dim3(32, BDIM, KS_N2E), 256>>>(node2edge, node_state,
                                            (float*)p_embp, EDIM, NDIM);
    k_red<<<512, 256>>>();
    k_prep<<<HDIM, 256>>>(edge_network);
    k_econv_tc<<<dim3(32, HSPLIT), 256, SM_ECONV>>>(edge_vec,
                                                    (const unsigned short*)p_enh,
                                                    (const unsigned short*)p_enl,
                                                    (float*)p_newp);
    k_nred<<<500, 256>>>((const float*)p_newp);
    k_gemm<<<dim3(16, BDIM, KS_AGG), 256>>>(edge2node, (const float*)p_new,
                                            (float*)p_aggp, NDIM, EDIM);
    k_norm<<<BDIM * NDIM, 256>>>(edge2node);
    k_fin<<<256, 256>>>(node_state, out);
}

// round 6
// speedup vs baseline: 4.3449x; 1.0201x over previous
#include <cuda_runtime.h>
#include <cuda_bf16.h>
#include <cstdint>

#define BDIM 2
#define NDIM 1000
#define EDIM 2000
#define HDIM 128
#define RTOT (BDIM * EDIM)          // 4000 flat rows

#define KS_N2E 8
#define KS_AGG 16
#define KCH    125
#define BK     25

#define HSPLIT 4                    // h-splits for tensor kernel
#define NH_PER (HDIM / HSPLIT)      // 32 h per block

// ---------------- scratch (device globals) ---------------------------------
__device__ float g_embp[(size_t)KS_N2E * RTOT * HDIM];
__device__ float g_emb [(size_t)RTOT * HDIM];
__device__ float g_new [(size_t)RTOT * HDIM];
__device__ float g_newp[(size_t)HSPLIT * RTOT * HDIM];
__device__ float g_aggp[(size_t)KS_AGG * BDIM * NDIM * HDIM];
__device__ float g_inv [(size_t)BDIM * NDIM];
// pre-split EN (bf16 hi/lo planes), plain [h][i][j] layout
__device__ unsigned short g_ENhi[(size_t)HDIM * 16384];
__device__ unsigned short g_ENlo[(size_t)HDIM * 16384];

// ---------------- f32x2 helpers (scalar GEMMs) ------------------------------
typedef unsigned long long ull;
__device__ __forceinline__ ull fma2(ull a, ull b, ull c) {
    ull d; asm("fma.rn.f32x2 %0, %1, %2, %3;" : "=l"(d) : "l"(a), "l"(b), "l"(c));
    return d;
}
__device__ __forceinline__ ull pack2(float lo, float hi) {
    ull d; asm("mov.b64 %0, {%1, %2};" : "=l"(d) : "f"(lo), "f"(hi)); return d;
}
__device__ __forceinline__ ull dup2(float x) { return pack2(x, x); }
__device__ __forceinline__ void unpack2(ull v, float& lo, float& hi) {
    asm("mov.b64 {%0, %1}, %2;" : "=f"(lo), "=f"(hi) : "l"(v));
}

// ---------------- mma.sync / cp.async helpers --------------------------------
__device__ __forceinline__ uint32_t smem_u32(const void* p) {
    uint32_t a;
    asm("{ .reg .u64 t; cvta.to.shared.u64 t, %1; cvt.u32.u64 %0, t; }"
        : "=r"(a) : "l"(p));
    return a;
}
__device__ __forceinline__ void ldsm4(uint32_t* r, uint32_t addr) {
    asm volatile("ldmatrix.sync.aligned.m8n8.x4.shared.b16 {%0,%1,%2,%3}, [%4];"
                 : "=r"(r[0]), "=r"(r[1]), "=r"(r[2]), "=r"(r[3]) : "r"(addr));
}
__device__ __forceinline__ void mma_bf16(float* d, const uint32_t* a,
                                         uint32_t b0, uint32_t b1) {
    asm volatile("mma.sync.aligned.m16n8k16.row.col.f32.bf16.bf16.f32 "
                 "{%0,%1,%2,%3}, {%4,%5,%6,%7}, {%8,%9}, {%0,%1,%2,%3};"
                 : "+f"(d[0]), "+f"(d[1]), "+f"(d[2]), "+f"(d[3])
                 : "r"(a[0]), "r"(a[1]), "r"(a[2]), "r"(a[3]), "r"(b0), "r"(b1));
}
__device__ __forceinline__ uint32_t cvt2(float lo, float hi) {
    uint32_t r;
    asm("cvt.rn.satfinite.bf16x2.f32 %0, %1, %2;" : "=r"(r) : "f"(hi), "f"(lo));
    return r;
}
__device__ __forceinline__ void cp16(uint32_t dst, const void* src) {
    asm volatile("cp.async.cg.shared.global [%0], [%1], 16;"
                 :: "r"(dst), "l"(src) : "memory");
}
__device__ __forceinline__ void cp_commit() {
    asm volatile("cp.async.commit_group;" ::: "memory");
}
__device__ __forceinline__ void cp_wait0() {
    asm volatile("cp.async.wait_group 0;" ::: "memory");
}

// ---------------------------------------------------------------------------
// Split-K scalar GEMM (proven; handles n2e and agg)
// ---------------------------------------------------------------------------
__global__ void __launch_bounds__(256) k_gemm(const float* __restrict__ A,
                                              const float* __restrict__ Bm,
                                              float* __restrict__ out,
                                              int ROWS, int KTOT) {
    __shared__ float As[64][BK + 1];
    __shared__ float Bs[BK][HDIM + 4];

    int b  = blockIdx.y;
    int z  = blockIdx.z;
    int r0 = blockIdx.x * 64;
    int t  = threadIdx.x;
    int lane = t & 31;
    int mg   = t >> 5;

    const float* Ab = A  + (size_t)b * ROWS * KTOT + (size_t)z * KCH;
    const float* Bb = Bm + (size_t)b * KTOT * HDIM + (size_t)z * KCH * HDIM;

    ull acc[8][2];
#pragma unroll
    for (int q = 0; q < 8; q++) { acc[q][0] = 0ull; acc[q][1] = 0ull; }

    for (int k0 = 0; k0 < KCH; k0 += BK) {
        for (int i = t; i < 64 * BK; i += 256) {
            int m = i / BK, k = i - m * BK;
            int r = r0 + m;
            As[m][k] = (r < ROWS) ? Ab[(size_t)r * KTOT + k0 + k] : 0.f;
        }
        for (int i = t; i < BK * HDIM; i += 256) {
            int k = i >> 7, h = i & 127;
            Bs[k][h] = Bb[(size_t)(k0 + k) * HDIM + h];
        }
        __syncthreads();
#pragma unroll
        for (int k = 0; k < BK; k++) {
            float4 bv = *(const float4*)&Bs[k][lane * 4];
            ull b01 = pack2(bv.x, bv.y);
            ull b23 = pack2(bv.z, bv.w);
#pragma unroll
            for (int q = 0; q < 8; q++) {
                ull a2 = dup2(As[mg * 8 + q][k]);
                acc[q][0] = fma2(a2, b01, acc[q][0]);
                acc[q][1] = fma2(a2, b23, acc[q][1]);
            }
        }
        __syncthreads();
    }

#pragma unroll
    for (int q = 0; q < 8; q++) {
        int r = r0 + mg * 8 + q;
        if (r < ROWS) {
            float4 v;
            unpack2(acc[q][0], v.x, v.y);
            unpack2(acc[q][1], v.z, v.w);
            *(float4*)&out[((size_t)z * BDIM * ROWS + (size_t)b * ROWS + r) * HDIM
                           + lane * 4] = v;
        }
    }
}

__global__ void __launch_bounds__(256) k_red() {
    const size_t STR = (size_t)RTOT * HDIM / 4;
    size_t f = (size_t)blockIdx.x * 256 + threadIdx.x;
    const float4* p = (const float4*)g_embp;
    float4 s = p[f];
#pragma unroll
    for (int z = 1; z < KS_N2E; z++) {
        float4 v = p[z * STR + f];
        s.x += v.x; s.y += v.y; s.z += v.z; s.w += v.w;
    }
    ((float4*)g_emb)[f] = s;
}

// ---------------------------------------------------------------------------
// Prep: split EN into bf16 hi/lo planes, plain [h][i][j]
// ---------------------------------------------------------------------------
__global__ void __launch_bounds__(256) k_prep(const float* __restrict__ EN) {
    int h = blockIdx.x;
    int t = threadIdx.x;
    const float* src = EN + (size_t)h * 16384;
    unsigned short* dh = g_ENhi + (size_t)h * 16384;
    unsigned short* dl = g_ENlo + (size_t)h * 16384;
    for (int idx = t; idx < 16384; idx += 256) {
        float v = src[idx];
        __nv_bfloat16 hb = __float2bfloat16(v);
        float hf = __bfloat162float(hb);
        __nv_bfloat16 lb = __float2bfloat16(v - hf);
        dh[idx] = *(unsigned short*)&hb;
        dl[idx] = *(unsigned short*)&lb;
    }
}

// ---------------------------------------------------------------------------
// Tensor-core econv via mma.sync, STATIC A + cp.async pipelined B.
// 512 threads = 16 warps; warp tile 32x32 (4x4 warp grid) -> 4 warps/SMSP.
//   tt = emb_tile @ EN_h^T (3-term bf16 split), acc += ev[r,h] * tt
// grid (32 M-tiles, HSPLIT). smem rows padded to 272B -> conflict-free ldsm.
// ---------------------------------------------------------------------------
#define ASTRB 272u
#define PLANE 34816u                 // 128 * 272
#define OFF_AH 0u
#define OFF_AL 34816u
#define OFF_B  69632u                // stage s at OFF_B + s*69632 (BH, then BL)
#define OFF_EV 208896u               // float [NH_PER][128]
#define SM_ECONV 225280u

__global__ void __launch_bounds__(512) k_econv_tc(const float* __restrict__ ev,
                                                  const unsigned short* __restrict__ ENhi,
                                                  const unsigned short* __restrict__ ENlo,
                                                  float* __restrict__ newp) {
    extern __shared__ char smraw[];
    uint32_t base32 = smem_u32(smraw);
    float* evs = (float*)(smraw + OFF_EV);

    int t = threadIdx.x;
    int lane = t & 31, w = t >> 5;
    int r0 = blockIdx.x * 128;
    int hbase = blockIdx.y * NH_PER;

    // ---- issue stage-0 B copy immediately (overlaps A build) ----
    {
        const char* sH = (const char*)(ENhi + (size_t)hbase * 16384);
        const char* sL = (const char*)(ENlo + (size_t)hbase * 16384);
        uint32_t dst = base32 + OFF_B;
#pragma unroll
        for (int k = 0; k < 4; k++) {
            int f = t + 512 * k;
            uint32_t i = (uint32_t)(f >> 4), seg = (uint32_t)(f & 15);
            uint32_t o = i * ASTRB + seg * 16u;
            cp16(dst + o,          sH + (size_t)f * 16);
            cp16(dst + PLANE + o,  sL + (size_t)f * 16);
        }
        cp_commit();
    }

    // ---- build static A (emb hi/lo bf16), straight from gmem ----
#pragma unroll 4
    for (int k = 0; k < 16; k++) {
        int p = t + 512 * k;                 // pair index 0..8191
        int m = p >> 6, jp = p & 63;
        int r = r0 + m;
        float2 e = (r < RTOT) ? *(const float2*)&g_emb[(size_t)r * HDIM + jp * 2]
                              : make_float2(0.f, 0.f);
        uint32_t hp = cvt2(e.x, e.y);
        float h0 = __uint_as_float(hp << 16);
        float h1 = __uint_as_float(hp & 0xFFFF0000u);
        uint32_t lp = cvt2(e.x - h0, e.y - h1);
        *(uint32_t*)(smraw + OFF_AH + (uint32_t)m * ASTRB + jp * 4) = hp;
        *(uint32_t*)(smraw + OFF_AL + (uint32_t)m * ASTRB + jp * 4) = lp;
    }
    // ---- stage ev slice ----
    for (int idx = t; idx < NH_PER * 128; idx += 512) {
        int hh = idx >> 7, m = idx & 127;
        int r = r0 + m;
        evs[hh * 128 + m] = (r < RTOT) ? ev[(size_t)r * HDIM + hbase + hh] : 0.f;
    }

    float acc[2][4][4];
#pragma unroll
    for (int ms = 0; ms < 2; ms++)
#pragma unroll
        for (int nt = 0; nt < 4; nt++)
#pragma unroll
            for (int q = 0; q < 4; q++) acc[ms][nt][q] = 0.f;

    int warpM = (w & 3) * 32;
    int warpN = (w >> 2) * 32;
    uint32_t aoff = (uint32_t)(warpM + (lane & 15)) * ASTRB + (uint32_t)(lane >> 4) * 16u;
    uint32_t boff = (uint32_t)(warpN + ((lane >> 4) & 1) * 8 + (lane & 7)) * ASTRB
                  + (uint32_t)((lane >> 3) & 1) * 16u;
    uint32_t AbH = base32 + OFF_AH + aoff;
    uint32_t AbL = base32 + OFF_AL + aoff;

    int rl0 = warpM + (lane >> 2);           // row-local index for ev fold

    for (int hh = 0; hh < NH_PER; hh++) {
        int s = hh & 1;
        cp_wait0();                          // stage s copy complete
        __syncthreads();                     // visible to all; readers of 1-s done

        if (hh + 1 < NH_PER) {               // issue stage 1-s for h+1
            const char* sH = (const char*)(ENhi + (size_t)(hbase + hh + 1) * 16384);
            const char* sL = (const char*)(ENlo + (size_t)(hbase + hh + 1) * 16384);
            uint32_t dst = base32 + OFF_B + (uint32_t)(1 - s) * 69632u;
#pragma unroll
            for (int k = 0; k < 4; k++) {
                int f = t + 512 * k;
                uint32_t i = (uint32_t)(f >> 4), seg = (uint32_t)(f & 15);
                uint32_t o = i * ASTRB + seg * 16u;
                cp16(dst + o,         sH + (size_t)f * 16);
                cp16(dst + PLANE + o, sL + (size_t)f * 16);
            }
            cp_commit();
        }

        uint32_t BbH = base32 + OFF_B + (uint32_t)s * 69632u + boff;
        uint32_t BbL = BbH + PLANE;

        float tt[2][4][4];
#pragma unroll
        for (int ms = 0; ms < 2; ms++)
#pragma unroll
            for (int nt = 0; nt < 4; nt++)
#pragma unroll
                for (int q = 0; q < 4; q++) tt[ms][nt][q] = 0.f;

#pragma unroll
        for (int ks = 0; ks < 8; ks++) {
            uint32_t ah0[4], ah1[4], al0[4], al1[4];
            ldsm4(ah0, AbH + ks * 32u);
            ldsm4(ah1, AbH + 4352u + ks * 32u);
            ldsm4(al0, AbL + ks * 32u);
            ldsm4(al1, AbL + 4352u + ks * 32u);
            uint32_t bh[2][4], bl[2][4];
#pragma unroll
            for (int np = 0; np < 2; np++) {
                ldsm4(bh[np], BbH + (uint32_t)np * 4352u + ks * 32u);
                ldsm4(bl[np], BbL + (uint32_t)np * 4352u + ks * 32u);
            }
#pragma unroll
            for (int nt = 0; nt < 4; nt++) {
                uint32_t b0h = bh[nt >> 1][(nt & 1) * 2];
                uint32_t b1h = bh[nt >> 1][(nt & 1) * 2 + 1];
                uint32_t b0l = bl[nt >> 1][(nt & 1) * 2];
                uint32_t b1l = bl[nt >> 1][(nt & 1) * 2 + 1];
                mma_bf16(tt[0][nt], ah0, b0h, b1h);   // AH*BH
                mma_bf16(tt[1][nt], ah1, b0h, b1h);
                mma_bf16(tt[0][nt], ah0, b0l, b1l);   // AH*BL
                mma_bf16(tt[1][nt], ah1, b0l, b1l);
                mma_bf16(tt[0][nt], al0, b0h, b1h);   // AL*BH
                mma_bf16(tt[1][nt], al1, b0h, b1h);
            }
        }

        // ---- fold ev[r,h]: acc += ev * tt ----
        const float* evh = evs + hh * 128;
        float ev0A = evh[rl0];            // ms=0, rows rl0
        float ev0B = evh[rl0 + 8];        // ms=0, rows rl0+8
        float ev1A = evh[rl0 + 16];       // ms=1
        float ev1B = evh[rl0 + 24];
#pragma unroll
        for (int nt = 0; nt < 4; nt++) {
            acc[0][nt][0] += ev0A * tt[0][nt][0];
            acc[0][nt][1] += ev0A * tt[0][nt][1];
            acc[0][nt][2] += ev0B * tt[0][nt][2];
            acc[0][nt][3] += ev0B * tt[0][nt][3];
            acc[1][nt][0] += ev1A * tt[1][nt][0];
            acc[1][nt][1] += ev1A * tt[1][nt][1];
            acc[1][nt][2] += ev1B * tt[1][nt][2];
            acc[1][nt][3] += ev1B * tt[1][nt][3];
        }
    }

    // ---- epilogue: write 32x32 warp patch to partial buffer ----
    size_t obase = (size_t)blockIdx.y * RTOT * HDIM;
#pragma unroll
    for (int ms = 0; ms < 2; ms++) {
        int rA = r0 + warpM + ms * 16 + (lane >> 2);
        int rB = rA + 8;
#pragma unroll
        for (int nt = 0; nt < 4; nt++) {
            int col = warpN + nt * 8 + (lane & 3) * 2;
            if (rA < RTOT)
                *(float2*)&newp[obase + (size_t)rA * HDIM + col] =
                    make_float2(acc[ms][nt][0], acc[ms][nt][1]);
            if (rB < RTOT)
                *(float2*)&newp[obase + (size_t)rB * HDIM + col] =
                    make_float2(acc[ms][nt][2], acc[ms][nt][3]);
        }
    }
}

// g_new = sum over HSPLIT partials
__global__ void __launch_bounds__(256) k_nred(const float* __restrict__ newp) {
    const size_t STR = (size_t)RTOT * HDIM / 4;
    size_t f = (size_t)blockIdx.x * 256 + threadIdx.x;
    const float4* p = (const float4*)newp;
    float4 s = p[f];
#pragma unroll
    for (int z = 1; z < HSPLIT; z++) {
        float4 v = p[z * STR + f];
        s.x += v.x; s.y += v.y; s.z += v.z; s.w += v.w;
    }
    ((float4*)g_new)[f] = s;
}

__global__ void __launch_bounds__(256) k_norm(const float* __restrict__ e2n) {
    __shared__ float red[256];
    int row = blockIdx.x;
    const float* p = e2n + (size_t)row * EDIM;
    float s = 0.f;
    for (int e = threadIdx.x; e < EDIM; e += 256) s += p[e];
    red[threadIdx.x] = s;
    __syncthreads();
    for (int o = 128; o > 0; o >>= 1) {
        if (threadIdx.x < o) red[threadIdx.x] += red[threadIdx.x + o];
        __syncthreads();
    }
    if (threadIdx.x == 0) g_inv[row] = 1.f / (1.f + red[0]);
}

__global__ void __launch_bounds__(256) k_fin(const float* __restrict__ ns,
                                             float* __restrict__ out) {
    const size_t STR = (size_t)BDIM * NDIM * HDIM / 4;
    size_t f = (size_t)blockIdx.x * 256 + threadIdx.x;
    const float4* p = (const float4*)g_aggp;
    float4 s = p[f];
#pragma unroll
    for (int z = 1; z < KS_AGG; z++) {
        float4 v = p[z * STR + f];
        s.x += v.x; s.y += v.y; s.z += v.z; s.w += v.w;
    }
    float4 n4 = ((const float4*)ns)[f];
    float inv = g_inv[(f * 4) >> 7];
    float4 o;
    o.x = (s.x + n4.x) * inv;
    o.y = (s.y + n4.y) * inv;
    o.z = (s.z + n4.z) * inv;
    o.w = (s.w + n4.w) * inv;
    ((float4*)out)[f] = o;
}

// ---------------------------------------------------------------------------
extern "C" void kernel_launch(void* const* d_in, const int* in_sizes, int n_in,
                              void* d_out, int out_size) {
    const float* node_state   = (const float*)d_in[0];
    const float* edge_vec     = (const float*)d_in[1];
    const float* node2edge    = (const float*)d_in[2];
    const float* edge2node    = (const float*)d_in[3];
    const float* edge_network = (const float*)d_in[4];
    float* out = (float*)d_out;

    void* p_embp; cudaGetSymbolAddress(&p_embp, g_embp);
    void* p_new;  cudaGetSymbolAddress(&p_new,  g_new);
    void* p_newp; cudaGetSymbolAddress(&p_newp, g_newp);
    void* p_aggp; cudaGetSymbolAddress(&p_aggp, g_aggp);
    void* p_enh;  cudaGetSymbolAddress(&p_enh,  g_ENhi);
    void* p_enl;  cudaGetSymbolAddress(&p_enl,  g_ENlo);

    cudaFuncSetAttribute(k_econv_tc, cudaFuncAttributeMaxDynamicSharedMemorySize,
                         SM_ECONV);

    k_gemm<<<dim3(32, BDIM, KS_N2E), 256>>>(node2edge, node_state,
                                            (float*)p_embp, EDIM, NDIM);
    k_red<<<512, 256>>>();
    k_prep<<<HDIM, 256>>>(edge_network);
    k_econv_tc<<<dim3(32, HSPLIT), 512, SM_ECONV>>>(edge_vec,
                                                    (const unsigned short*)p_enh,
                                                    (const unsigned short*)p_enl,
                                                    (float*)p_newp);
    k_nred<<<500, 256>>>((const float*)p_newp);
    k_gemm<<<dim3(16, BDIM, KS_AGG), 256>>>(edge2node, (const float*)p_new,
                                            (float*)p_aggp, NDIM, EDIM);
    k_norm<<<BDIM * NDIM, 256>>>(edge2node);
    k_fin<<<256, 256>>>(node_state, out);
}

// round 8
// speedup vs baseline: 5.6752x; 1.3062x over previous
#include <cuda_runtime.h>
#include <cuda_bf16.h>
#include <cstdint>

#define BDIM 2
#define NDIM 1000
#define EDIM 2000
#define HDIM 128
#define RTOT (BDIM * EDIM)          // 4000 flat rows

#define HSPLIT 4                    // h-splits for econv tensor kernel
#define NH_PER (HDIM / HSPLIT)      // 32 h per block

#define ZN2E 4                      // split-K for n2e tc-gemm (K=1000 -> 250)
#define ZAGG 8                      // split-K for agg tc-gemm (K=2000 -> 250)
#define KCH2 250

// ---------------- scratch (device globals) ---------------------------------
__device__ float g_embp[(size_t)ZN2E * RTOT * HDIM];          // n2e partials
__device__ float g_emb [(size_t)RTOT * HDIM];
__device__ float g_newp[(size_t)HSPLIT * RTOT * HDIM];        // econv partials
__device__ float g_newT[(size_t)BDIM * HDIM * EDIM];          // new_n2e^T [b][i][e]
__device__ float g_aggp[(size_t)ZAGG * BDIM * NDIM * HDIM];   // agg partials
__device__ float g_inv [(size_t)BDIM * NDIM];
__device__ float g_nsT [(size_t)BDIM * HDIM * NDIM];          // node_state^T
// pre-split EN (bf16 hi/lo planes), plain [h][i][j] layout
__device__ unsigned short g_ENhi[(size_t)HDIM * 16384];
__device__ unsigned short g_ENlo[(size_t)HDIM * 16384];

// ---------------- mma.sync / cp.async helpers --------------------------------
__device__ __forceinline__ uint32_t smem_u32(const void* p) {
    uint32_t a;
    asm("{ .reg .u64 t; cvta.to.shared.u64 t, %1; cvt.u32.u64 %0, t; }"
        : "=r"(a) : "l"(p));
    return a;
}
__device__ __forceinline__ void ldsm4(uint32_t* r, uint32_t addr) {
    asm volatile("ldmatrix.sync.aligned.m8n8.x4.shared.b16 {%0,%1,%2,%3}, [%4];"
                 : "=r"(r[0]), "=r"(r[1]), "=r"(r[2]), "=r"(r[3]) : "r"(addr));
}
__device__ __forceinline__ void mma_bf16(float* d, const uint32_t* a,
                                         uint32_t b0, uint32_t b1) {
    asm volatile("mma.sync.aligned.m16n8k16.row.col.f32.bf16.bf16.f32 "
                 "{%0,%1,%2,%3}, {%4,%5,%6,%7}, {%8,%9}, {%0,%1,%2,%3};"
                 : "+f"(d[0]), "+f"(d[1]), "+f"(d[2]), "+f"(d[3])
                 : "r"(a[0]), "r"(a[1]), "r"(a[2]), "r"(a[3]), "r"(b0), "r"(b1));
}
__device__ __forceinline__ uint32_t cvt2(float lo, float hi) {
    uint32_t r;
    asm("cvt.rn.satfinite.bf16x2.f32 %0, %1, %2;" : "=r"(r) : "f"(hi), "f"(lo));
    return r;
}
__device__ __forceinline__ void cp16(uint32_t dst, const void* src) {
    asm volatile("cp.async.cg.shared.global [%0], [%1], 16;"
                 :: "r"(dst), "l"(src) : "memory");
}
__device__ __forceinline__ void cp_commit() {
    asm volatile("cp.async.commit_group;" ::: "memory");
}
__device__ __forceinline__ void cp_wait0() {
    asm volatile("cp.async.wait_group 0;" ::: "memory");
}

// ---------------------------------------------------------------------------
// Tile transpose: in [b][R][C] -> out [b][C][R]
// ---------------------------------------------------------------------------
__global__ void __launch_bounds__(256) k_tr(const float* __restrict__ in,
                                            float* __restrict__ out,
                                            int R, int C) {
    __shared__ float tile[32][33];
    int b = blockIdx.z;
    const float* inb = in + (size_t)b * R * C;
    float* outb = out + (size_t)b * C * R;
    int rbase = blockIdx.x * 32, cbase = blockIdx.y * 32;
    for (int rr = threadIdx.y; rr < 32; rr += 8) {
        int r = rbase + rr, c = cbase + threadIdx.x;
        tile[rr][threadIdx.x] = (r < R && c < C) ? inb[(size_t)r * C + c] : 0.f;
    }
    __syncthreads();
    for (int cc = threadIdx.y; cc < 32; cc += 8) {
        int c = cbase + cc, r = rbase + threadIdx.x;
        if (c < C && r < R) outb[(size_t)c * R + r] = tile[threadIdx.x][cc];
    }
}

// ---------------------------------------------------------------------------
// Tensor-core split-K GEMM (3-term bf16 split):
//   out[z][b][r][i] = sum_{k in chunk z} A[b][r][k] * BT[b][i][k]
// M-tile 128 x N=128, K-chunk 250 (4 sub-tiles of 64, last 58 zero-padded).
// 512 threads, 16 warps, warp tile 32x32 -- identical fragment layout to econv.
// ---------------------------------------------------------------------------
#define TSTR 144u                   // (64 bf16 = 128B) + 16B pad
#define OFF2_AH 0u
#define OFF2_AL 18432u              // 128*144
#define OFF2_BH 36864u
#define OFF2_BL 55296u
#define SM_GEMM2 73728u

__global__ void __launch_bounds__(512) k_gemm_tc(const float* __restrict__ A,
                                                 const float* __restrict__ BT,
                                                 float* __restrict__ out,
                                                 int ROWS, int KTOT) {
    extern __shared__ char smraw[];
    uint32_t base32 = smem_u32(smraw);

    int t = threadIdx.x;
    int lane = t & 31, w = t >> 5;
    int b  = blockIdx.y;
    int z  = blockIdx.z;
    int r0 = blockIdx.x * 128;

    const float* Ab  = A  + (size_t)b * ROWS * KTOT;
    const float* BTb = BT + (size_t)b * HDIM * KTOT;

    float acc[2][4][4];
#pragma unroll
    for (int ms = 0; ms < 2; ms++)
#pragma unroll
        for (int nt = 0; nt < 4; nt++)
#pragma unroll
            for (int q = 0; q < 4; q++) acc[ms][nt][q] = 0.f;

    int warpM = (w & 3) * 32;
    int warpN = (w >> 2) * 32;
    uint32_t aoff = (uint32_t)(warpM + (lane & 15)) * TSTR + (uint32_t)(lane >> 4) * 16u;
    uint32_t boff = (uint32_t)(warpN + ((lane >> 4) & 1) * 8 + (lane & 7)) * TSTR
                  + (uint32_t)((lane >> 3) & 1) * 16u;
    uint32_t AbH = base32 + OFF2_AH + aoff;
    uint32_t AbL = base32 + OFF2_AL + aoff;
    uint32_t BbH = base32 + OFF2_BH + boff;
    uint32_t BbL = base32 + OFF2_BL + boff;

    for (int kc = 0; kc < 4; kc++) {
        int k0 = z * KCH2 + kc * 64;
        int kw = KCH2 - kc * 64; if (kw > 64) kw = 64;   // 64,64,64,58
        __syncthreads();
        // ---- load + split A tile [128][64] ----
#pragma unroll
        for (int q = 0; q < 8; q++) {
            int p = t + 512 * q;               // pair index 0..4095
            int m = p >> 5, jp = p & 31;
            int r = r0 + m;
            float x = 0.f, y = 0.f;
            if (r < ROWS) {
                const float* ar = Ab + (size_t)r * KTOT + k0;
                if (jp * 2 < kw)     x = ar[jp * 2];
                if (jp * 2 + 1 < kw) y = ar[jp * 2 + 1];
            }
            uint32_t hp = cvt2(x, y);
            float h0 = __uint_as_float(hp << 16);
            float h1 = __uint_as_float(hp & 0xFFFF0000u);
            uint32_t lp = cvt2(x - h0, y - h1);
            *(uint32_t*)(smraw + OFF2_AH + (uint32_t)m * TSTR + jp * 4) = hp;
            *(uint32_t*)(smraw + OFF2_AL + (uint32_t)m * TSTR + jp * 4) = lp;
        }
        // ---- load + split B tile [128][64] (BT rows = i) ----
#pragma unroll
        for (int q = 0; q < 8; q++) {
            int p = t + 512 * q;
            int i = p >> 5, jp = p & 31;
            const float* br = BTb + (size_t)i * KTOT + k0;
            float x = 0.f, y = 0.f;
            if (jp * 2 < kw)     x = br[jp * 2];
            if (jp * 2 + 1 < kw) y = br[jp * 2 + 1];
            uint32_t hp = cvt2(x, y);
            float h0 = __uint_as_float(hp << 16);
            float h1 = __uint_as_float(hp & 0xFFFF0000u);
            uint32_t lp = cvt2(x - h0, y - h1);
            *(uint32_t*)(smraw + OFF2_BH + (uint32_t)i * TSTR + jp * 4) = hp;
            *(uint32_t*)(smraw + OFF2_BL + (uint32_t)i * TSTR + jp * 4) = lp;
        }
        __syncthreads();

#pragma unroll
        for (int ks = 0; ks < 4; ks++) {
            uint32_t ah0[4], ah1[4], al0[4], al1[4];
            ldsm4(ah0, AbH + ks * 32u);
            ldsm4(ah1, AbH + 2304u + ks * 32u);      // +16 rows
            ldsm4(al0, AbL + ks * 32u);
            ldsm4(al1, AbL + 2304u + ks * 32u);
            uint32_t bh[2][4], bl[2][4];
#pragma unroll
            for (int np = 0; np < 2; np++) {
                ldsm4(bh[np], BbH + (uint32_t)np * 2304u + ks * 32u);
                ldsm4(bl[np], BbL + (uint32_t)np * 2304u + ks * 32u);
            }
#pragma unroll
            for (int nt = 0; nt < 4; nt++) {
                uint32_t b0h = bh[nt >> 1][(nt & 1) * 2];
                uint32_t b1h = bh[nt >> 1][(nt & 1) * 2 + 1];
                uint32_t b0l = bl[nt >> 1][(nt & 1) * 2];
                uint32_t b1l = bl[nt >> 1][(nt & 1) * 2 + 1];
                mma_bf16(acc[0][nt], ah0, b0h, b1h);   // AH*BH
                mma_bf16(acc[1][nt], ah1, b0h, b1h);
                mma_bf16(acc[0][nt], ah0, b0l, b1l);   // AH*BL
                mma_bf16(acc[1][nt], ah1, b0l, b1l);
                mma_bf16(acc[0][nt], al0, b0h, b1h);   // AL*BH
                mma_bf16(acc[1][nt], al1, b0h, b1h);
            }
        }
    }

    // ---- epilogue: partial write [z][b][r][i] ----
#pragma unroll
    for (int ms = 0; ms < 2; ms++) {
        int rA = r0 + warpM + ms * 16 + (lane >> 2);
        int rB = rA + 8;
#pragma unroll
        for (int nt = 0; nt < 4; nt++) {
            int col = warpN + nt * 8 + (lane & 3) * 2;
            if (rA < ROWS)
                *(float2*)&out[((size_t)z * BDIM * ROWS + (size_t)b * ROWS + rA)
                               * HDIM + col] =
                    make_float2(acc[ms][nt][0], acc[ms][nt][1]);
            if (rB < ROWS)
                *(float2*)&out[((size_t)z * BDIM * ROWS + (size_t)b * ROWS + rB)
                               * HDIM + col] =
                    make_float2(acc[ms][nt][2], acc[ms][nt][3]);
        }
    }
}

// g_emb = sum_z g_embp[z]     (grid 500 exactly covers RTOT*HDIM/4)
__global__ void __launch_bounds__(256) k_red() {
    const size_t STR = (size_t)RTOT * HDIM / 4;
    size_t f = (size_t)blockIdx.x * 256 + threadIdx.x;
    const float4* p = (const float4*)g_embp;
    float4 s = p[f];
#pragma unroll
    for (int z = 1; z < ZN2E; z++) {
        float4 v = p[z * STR + f];
        s.x += v.x; s.y += v.y; s.z += v.z; s.w += v.w;
    }
    ((float4*)g_emb)[f] = s;
}

// ---------------------------------------------------------------------------
// Prep: split EN into bf16 hi/lo planes, plain [h][i][j]
// ---------------------------------------------------------------------------
__global__ void __launch_bounds__(256) k_prep(const float* __restrict__ EN) {
    int h = blockIdx.x;
    int t = threadIdx.x;
    const float* src = EN + (size_t)h * 16384;
    unsigned short* dh = g_ENhi + (size_t)h * 16384;
    unsigned short* dl = g_ENlo + (size_t)h * 16384;
    for (int idx = t; idx < 16384; idx += 256) {
        float v = src[idx];
        __nv_bfloat16 hb = __float2bfloat16(v);
        float hf = __bfloat162float(hb);
        __nv_bfloat16 lb = __float2bfloat16(v - hf);
        dh[idx] = *(unsigned short*)&hb;
        dl[idx] = *(unsigned short*)&lb;
    }
}

// ---------------------------------------------------------------------------
// Tensor-core econv (unchanged from r6): static A + cp.async pipelined B.
// ---------------------------------------------------------------------------
#define ASTRB 272u
#define PLANE 34816u
#define OFF_AH 0u
#define OFF_AL 34816u
#define OFF_B  69632u
#define OFF_EV 208896u
#define SM_ECONV 225280u

__global__ void __launch_bounds__(512) k_econv_tc(const float* __restrict__ ev,
                                                  const unsigned short* __restrict__ ENhi,
                                                  const unsigned short* __restrict__ ENlo,
                                                  float* __restrict__ newp) {
    extern __shared__ char smraw[];
    uint32_t base32 = smem_u32(smraw);
    float* evs = (float*)(smraw + OFF_EV);

    int t = threadIdx.x;
    int lane = t & 31, w = t >> 5;
    int r0 = blockIdx.x * 128;
    int hbase = blockIdx.y * NH_PER;

    {
        const char* sH = (const char*)(ENhi + (size_t)hbase * 16384);
        const char* sL = (const char*)(ENlo + (size_t)hbase * 16384);
        uint32_t dst = base32 + OFF_B;
#pragma unroll
        for (int k = 0; k < 4; k++) {
            int f = t + 512 * k;
            uint32_t i = (uint32_t)(f >> 4), seg = (uint32_t)(f & 15);
            uint32_t o = i * ASTRB + seg * 16u;
            cp16(dst + o,          sH + (size_t)f * 16);
            cp16(dst + PLANE + o,  sL + (size_t)f * 16);
        }
        cp_commit();
    }

#pragma unroll 4
    for (int k = 0; k < 16; k++) {
        int p = t + 512 * k;
        int m = p >> 6, jp = p & 63;
        int r = r0 + m;
        float2 e = (r < RTOT) ? *(const float2*)&g_emb[(size_t)r * HDIM + jp * 2]
                              : make_float2(0.f, 0.f);
        uint32_t hp = cvt2(e.x, e.y);
        float h0 = __uint_as_float(hp << 16);
        float h1 = __uint_as_float(hp & 0xFFFF0000u);
        uint32_t lp = cvt2(e.x - h0, e.y - h1);
        *(uint32_t*)(smraw + OFF_AH + (uint32_t)m * ASTRB + jp * 4) = hp;
        *(uint32_t*)(smraw + OFF_AL + (uint32_t)m * ASTRB + jp * 4) = lp;
    }
    for (int idx = t; idx < NH_PER * 128; idx += 512) {
        int hh = idx >> 7, m = idx & 127;
        int r = r0 + m;
        evs[hh * 128 + m] = (r < RTOT) ? ev[(size_t)r * HDIM + hbase + hh] : 0.f;
    }

    float acc[2][4][4];
#pragma unroll
    for (int ms = 0; ms < 2; ms++)
#pragma unroll
        for (int nt = 0; nt < 4; nt++)
#pragma unroll
            for (int q = 0; q < 4; q++) acc[ms][nt][q] = 0.f;

    int warpM = (w & 3) * 32;
    int warpN = (w >> 2) * 32;
    uint32_t aoff = (uint32_t)(warpM + (lane & 15)) * ASTRB + (uint32_t)(lane >> 4) * 16u;
    uint32_t boff = (uint32_t)(warpN + ((lane >> 4) & 1) * 8 + (lane & 7)) * ASTRB
                  + (uint32_t)((lane >> 3) & 1) * 16u;
    uint32_t AbH = base32 + OFF_AH + aoff;
    uint32_t AbL = base32 + OFF_AL + aoff;

    int rl0 = warpM + (lane >> 2);

    for (int hh = 0; hh < NH_PER; hh++) {
        int s = hh & 1;
        cp_wait0();
        __syncthreads();

        if (hh + 1 < NH_PER) {
            const char* sH = (const char*)(ENhi + (size_t)(hbase + hh + 1) * 16384);
            const char* sL = (const char*)(ENlo + (size_t)(hbase + hh + 1) * 16384);
            uint32_t dst = base32 + OFF_B + (uint32_t)(1 - s) * 69632u;
#pragma unroll
            for (int k = 0; k < 4; k++) {
                int f = t + 512 * k;
                uint32_t i = (uint32_t)(f >> 4), seg = (uint32_t)(f & 15);
                uint32_t o = i * ASTRB + seg * 16u;
                cp16(dst + o,         sH + (size_t)f * 16);
                cp16(dst + PLANE + o, sL + (size_t)f * 16);
            }
            cp_commit();
        }

        uint32_t BbH = base32 + OFF_B + (uint32_t)s * 69632u + boff;
        uint32_t BbL = BbH + PLANE;

        float tt[2][4][4];
#pragma unroll
        for (int ms = 0; ms < 2; ms++)
#pragma unroll
            for (int nt = 0; nt < 4; nt++)
#pragma unroll
                for (int q = 0; q < 4; q++) tt[ms][nt][q] = 0.f;

#pragma unroll
        for (int ks = 0; ks < 8; ks++) {
            uint32_t ah0[4], ah1[4], al0[4], al1[4];
            ldsm4(ah0, AbH + ks * 32u);
            ldsm4(ah1, AbH + 4352u + ks * 32u);
            ldsm4(al0, AbL + ks * 32u);
            ldsm4(al1, AbL + 4352u + ks * 32u);
            uint32_t bh[2][4], bl[2][4];
#pragma unroll
            for (int np = 0; np < 2; np++) {
                ldsm4(bh[np], BbH + (uint32_t)np * 4352u + ks * 32u);
                ldsm4(bl[np], BbL + (uint32_t)np * 4352u + ks * 32u);
            }
#pragma unroll
            for (int nt = 0; nt < 4; nt++) {
                uint32_t b0h = bh[nt >> 1][(nt & 1) * 2];
                uint32_t b1h = bh[nt >> 1][(nt & 1) * 2 + 1];
                uint32_t b0l = bl[nt >> 1][(nt & 1) * 2];
                uint32_t b1l = bl[nt >> 1][(nt & 1) * 2 + 1];
                mma_bf16(tt[0][nt], ah0, b0h, b1h);
                mma_bf16(tt[1][nt], ah1, b0h, b1h);
                mma_bf16(tt[0][nt], ah0, b0l, b1l);
                mma_bf16(tt[1][nt], ah1, b0l, b1l);
                mma_bf16(tt[0][nt], al0, b0h, b1h);
                mma_bf16(tt[1][nt], al1, b0h, b1h);
            }
        }

        const float* evh = evs + hh * 128;
        float ev0A = evh[rl0];
        float ev0B = evh[rl0 + 8];
        float ev1A = evh[rl0 + 16];
        float ev1B = evh[rl0 + 24];
#pragma unroll
        for (int nt = 0; nt < 4; nt++) {
            acc[0][nt][0] += ev0A * tt[0][nt][0];
            acc[0][nt][1] += ev0A * tt[0][nt][1];
            acc[0][nt][2] += ev0B * tt[0][nt][2];
            acc[0][nt][3] += ev0B * tt[0][nt][3];
            acc[1][nt][0] += ev1A * tt[1][nt][0];
            acc[1][nt][1] += ev1A * tt[1][nt][1];
            acc[1][nt][2] += ev1B * tt[1][nt][2];
            acc[1][nt][3] += ev1B * tt[1][nt][3];
        }
    }

    size_t obase = (size_t)blockIdx.y * RTOT * HDIM;
#pragma unroll
    for (int ms = 0; ms < 2; ms++) {
        int rA = r0 + warpM + ms * 16 + (lane >> 2);
        int rB = rA + 8;
#pragma unroll
        for (int nt = 0; nt < 4; nt++) {
            int col = warpN + nt * 8 + (lane & 3) * 2;
            if (rA < RTOT)
                *(float2*)&newp[obase + (size_t)rA * HDIM + col] =
                    make_float2(acc[ms][nt][0], acc[ms][nt][1]);
            if (rB < RTOT)
                *(float2*)&newp[obase + (size_t)rB * HDIM + col] =
                    make_float2(acc[ms][nt][2], acc[ms][nt][3]);
        }
    }
}

// g_newT[b][i][e] = sum over HSPLIT partials (transposed write), grid 500
__global__ void __launch_bounds__(256) k_nred(const float* __restrict__ newp) {
    const size_t STR = (size_t)RTOT * HDIM / 4;
    size_t f = (size_t)blockIdx.x * 256 + threadIdx.x;
    const float4* p = (const float4*)newp;
    float4 s = p[f];
#pragma unroll
    for (int z = 1; z < HSPLIT; z++) {
        float4 v = p[z * STR + f];
        s.x += v.x; s.y += v.y; s.z += v.z; s.w += v.w;
    }
    int r  = (int)(f >> 5);                  // global row (b*E + e)
    int c0 = (int)(f & 31) * 4;              // column i
    int b  = r / EDIM, e = r - b * EDIM;
    float* o = g_newT + ((size_t)b * HDIM) * EDIM + e;
    o[(size_t)(c0 + 0) * EDIM] = s.x;
    o[(size_t)(c0 + 1) * EDIM] = s.y;
    o[(size_t)(c0 + 2) * EDIM] = s.z;
    o[(size_t)(c0 + 3) * EDIM] = s.w;
}

__global__ void __launch_bounds__(256) k_norm(const float* __restrict__ e2n) {
    __shared__ float red[256];
    int row = blockIdx.x;
    const float* p = e2n + (size_t)row * EDIM;
    float s = 0.f;
    for (int e = threadIdx.x; e < EDIM; e += 256) s += p[e];
    red[threadIdx.x] = s;
    __syncthreads();
    for (int o = 128; o > 0; o >>= 1) {
        if (threadIdx.x < o) red[threadIdx.x] += red[threadIdx.x + o];
        __syncthreads();
    }
    if (threadIdx.x == 0) g_inv[row] = 1.f / (1.f + red[0]);
}

// out = (sum_z g_aggp[z] + node_state) * g_inv    (grid 250 exact)
__global__ void __launch_bounds__(256) k_fin(const float* __restrict__ ns,
                                             float* __restrict__ out) {
    const size_t STR = (size_t)BDIM * NDIM * HDIM / 4;
    size_t f = (size_t)blockIdx.x * 256 + threadIdx.x;
    const float4* p = (const float4*)g_aggp;
    float4 s = p[f];
#pragma unroll
    for (int z = 1; z < ZAGG; z++) {
        float4 v = p[z * STR + f];
        s.x += v.x; s.y += v.y; s.z += v.z; s.w += v.w;
    }
    float4 n4 = ((const float4*)ns)[f];
    float inv = g_inv[(f * 4) >> 7];
    float4 o;
    o.x = (s.x + n4.x) * inv;
    o.y = (s.y + n4.y) * inv;
    o.z = (s.z + n4.z) * inv;
    o.w = (s.w + n4.w) * inv;
    ((float4*)out)[f] = o;
}

// ---------------------------------------------------------------------------
extern "C" void kernel_launch(void* const* d_in, const int* in_sizes, int n_in,
                              void* d_out, int out_size) {
    const float* node_state   = (const float*)d_in[0];
    const float* edge_vec     = (const float*)d_in[1];
    const float* node2edge    = (const float*)d_in[2];
    const float* edge2node    = (const float*)d_in[3];
    const float* edge_network = (const float*)d_in[4];
    float* out = (float*)d_out;

    void* p_embp; cudaGetSymbolAddress(&p_embp, g_embp);
    void* p_newp; cudaGetSymbolAddress(&p_newp, g_newp);
    void* p_newT; cudaGetSymbolAddress(&p_newT, g_newT);
    void* p_aggp; cudaGetSymbolAddress(&p_aggp, g_aggp);
    void* p_nsT;  cudaGetSymbolAddress(&p_nsT,  g_nsT);
    void* p_enh;  cudaGetSymbolAddress(&p_enh,  g_ENhi);
    void* p_enl;  cudaGetSymbolAddress(&p_enl,  g_ENlo);

    cudaFuncSetAttribute(k_econv_tc, cudaFuncAttributeMaxDynamicSharedMemorySize,
                         SM_ECONV);
    cudaFuncSetAttribute(k_gemm_tc, cudaFuncAttributeMaxDynamicSharedMemorySize,
                         SM_GEMM2);

    // node_state^T: [b][1000][128] -> [b][128][1000]
    k_tr<<<dim3(32, 4, BDIM), dim3(32, 8)>>>(node_state, (float*)p_nsT,
                                             NDIM, HDIM);
    k_prep<<<HDIM, 256>>>(edge_network);
    // n2e: A=node2edge [b][E][N], BT=nsT -> partials (16,2,4)=128 blocks
    k_gemm_tc<<<dim3(16, BDIM, ZN2E), 512, SM_GEMM2>>>(node2edge,
                                                       (const float*)p_nsT,
                                                       (float*)p_embp,
                                                       EDIM, NDIM);
    k_red<<<500, 256>>>();
    k_econv_tc<<<dim3(32, HSPLIT), 512, SM_ECONV>>>(edge_vec,
                                                    (const unsigned short*)p_enh,
                                                    (const unsigned short*)p_enl,
                                                    (float*)p_newp);
    k_nred<<<500, 256>>>((const float*)p_newp);
    // agg: A=edge2node [b][N][E], BT=g_newT -> partials (8,2,8)=128 blocks
    k_gemm_tc<<<dim3(8, BDIM, ZAGG), 512, SM_GEMM2>>>(edge2node,
                                                      (const float*)p_newT,
                                                      (float*)p_aggp,
                                                      NDIM, EDIM);
    k_norm<<<BDIM * NDIM, 256>>>(edge2node);
    k_fin<<<250, 256>>>(node_state, out);
}